// round 7
// baseline (speedup 1.0000x reference)
#include <cuda_runtime.h>
#include <math.h>
#include <stdint.h>

// Problem constants
#define B_   8
#define C_   512
#define HW_  1024
#define D_   512
#define NH_  8
#define HD_  64
#define L_   77
#define DC_  768
#define FF_  2048
#define M_   (B_ * HW_)   // 8192 tokens

// ---------------- scratch (no allocation allowed -> __device__ globals) ----
__device__ float g_H[(size_t)M_ * D_];   // running hidden state
__device__ float g_X[(size_t)M_ * D_];   // GN / LN outputs
__device__ float g_Q[(size_t)M_ * D_];
__device__ float g_K[(size_t)M_ * D_];
__device__ float g_V[(size_t)M_ * D_];
__device__ float g_A[(size_t)M_ * D_];   // attention output
__device__ float g_F[(size_t)M_ * FF_];  // FF hidden
__device__ float g_WT[4980736];          // transposed weights [N,K]

// WT offsets
#define OF_PIN 0
#define OF_Q1  262144
#define OF_K1  524288
#define OF_V1  786432
#define OF_O1  1048576
#define OF_Q2  1310720
#define OF_K2  1572864
#define OF_V2  1966080
#define OF_O2  2359296
#define OF_FF1 2621440
#define OF_FF2 3670016
#define OF_PO  4718592

// ======================= mma.sync tf32 helpers ============================
__device__ __forceinline__ uint32_t f2tf32(float f) {
    uint32_t o;
    asm("cvt.rna.tf32.f32 %0, %1;" : "=r"(o) : "f"(f));
    return o;
}

__device__ __forceinline__ void mma_tf32(float* d, const uint32_t* a,
                                         const uint32_t* b) {
    asm volatile(
        "mma.sync.aligned.m16n8k8.row.col.f32.tf32.tf32.f32 "
        "{%0,%1,%2,%3}, {%4,%5,%6,%7}, {%8,%9}, {%0,%1,%2,%3};\n"
        : "+f"(d[0]), "+f"(d[1]), "+f"(d[2]), "+f"(d[3])
        : "r"(a[0]), "r"(a[1]), "r"(a[2]), "r"(a[3]),
          "r"(b[0]), "r"(b[1]));
}

// ======================= weight transpose [K,N] -> [N,K] ===================
__global__ __launch_bounds__(256) void transpose_kernel(
    const float* __restrict__ in, float* __restrict__ out, int K, int N)
{
    __shared__ float t[32][33];
    const int n0 = blockIdx.x * 32, k0 = blockIdx.y * 32;
    const int x = threadIdx.x, y = threadIdx.y;
#pragma unroll
    for (int i = 0; i < 32; i += 8)
        t[y + i][x] = in[(size_t)(k0 + y + i) * N + n0 + x];
    __syncthreads();
#pragma unroll
    for (int i = 0; i < 32; i += 8)
        out[(size_t)(n0 + y + i) * K + k0 + x] = t[x][y + i];
}

// ======================= tensor-core tf32 GEMM ============================
// out[M,N] = A[M,K] @ Wt[N,K]^T (+bias). Modes:
//   0: bias; 1: bias+GELU; 2: bias+resid[M,N]; 3: BCHW out + bias + resid
// CTA 128x128, 8 warps (4x2), warp tile 32x64, K chunk 32, double-buffered.
// Smem frag layout (floats), reg-major so fills are st.128 and reads lds.32:
//   A: (((m_atom*4 + k_atom)*4 + reg)*32 + lane)   8*4*4*32 = 4096 f = 16KB
//   B: (((n_atom*4 + k_atom)*2 + reg)*32 + lane)  16*4*2*32 = 4096 f = 16KB
#define GEMM_SMEM_BYTES 68608   // 1024 + max(4*16KB frags, 128*132*4 stage)

__global__ __launch_bounds__(256) void tc_gemm_kernel(
    const float* __restrict__ A, const float* __restrict__ Wt,
    const float* __restrict__ bias, const float* __restrict__ resid,
    float* __restrict__ out, int M, int N, int K, int mode)
{
    extern __shared__ char smem[];
    float* const sA0 = (float*)(smem + 1024);
    float* const sB0 = sA0 + 4096;
    float* const sA1 = sB0 + 4096;
    float* const sB1 = sA1 + 4096;

    const int tid  = threadIdx.x;
    const int wid  = tid >> 5, lane = tid & 31;
    const int c8   = tid & 7,  r8   = tid >> 3;     // fill mapping
    const int m0   = blockIdx.y * 128;
    const int n0   = blockIdx.x * 128;
    const int wm   = wid >> 1, wn = wid & 1;        // 4 x 2 warps
    const int nchunk = K >> 5;

    float acc[2][8][4];
#pragma unroll
    for (int i = 0; i < 2; i++)
#pragma unroll
        for (int j = 0; j < 8; j++)
#pragma unroll
            for (int r = 0; r < 4; r++) acc[i][j][r] = 0.f;

    uint4 pa[4], pb[4];

    // ---- prefetch chunk ck into regs (tf32-converted) ----
    auto LDCHUNK = [&](int ck) {
        const int k0 = ck << 5;
#pragma unroll
        for (int i = 0; i < 4; i++) {
            const int r = r8 + 32 * i;
            float4 va = make_float4(0.f, 0.f, 0.f, 0.f);
            if (m0 + r < M)
                va = *(const float4*)(A + (size_t)(m0 + r) * K + k0 + 4 * c8);
            pa[i].x = f2tf32(va.x); pa[i].y = f2tf32(va.y);
            pa[i].z = f2tf32(va.z); pa[i].w = f2tf32(va.w);
            float4 vb = *(const float4*)(Wt + (size_t)(n0 + r) * K + k0 + 4 * c8);
            pb[i].x = f2tf32(vb.x); pb[i].y = f2tf32(vb.y);
            pb[i].z = f2tf32(vb.z); pb[i].w = f2tf32(vb.w);
        }
    };
    // ---- store prefetched regs into smem fragment layout ----
    auto STCHUNK = [&](int bsel) {
        float* const sa = bsel ? sA1 : sA0;
        float* const sb = bsel ? sB1 : sB0;
        const int k_atom = c8 >> 1;
#pragma unroll
        for (int i = 0; i < 4; i++) {
            const int r = r8 + 32 * i;
            {   // A: element rows (m), tf32 frag a-regs
                const int m_atom = r >> 4, ra = r & 15;
                const int reg = (c8 & 1) * 2 + (ra >= 8 ? 1 : 0);
                const int off = (((m_atom * 4 + k_atom) * 4 + reg) * 32 + (ra & 7) * 4);
                *(uint4*)(sa + off) = pa[i];
            }
            {   // B: element rows are n, frag b-regs
                const int n_atom = r >> 3, rn = r & 7;
                const int reg = c8 & 1;
                const int off = (((n_atom * 4 + k_atom) * 2 + reg) * 32 + rn * 4);
                *(uint4*)(sb + off) = pb[i];
            }
        }
    };
    // ---- compute one chunk from smem ----
    auto COMPUTE = [&](int bsel) {
        const float* const sa = bsel ? sA1 : sA0;
        const float* const sb = bsel ? sB1 : sB0;
#pragma unroll
        for (int ka = 0; ka < 4; ka++) {
            uint32_t af[2][4], bf[8][2];
#pragma unroll
            for (int im = 0; im < 2; im++) {
                const int ma = wm * 2 + im;
#pragma unroll
                for (int r = 0; r < 4; r++)
                    af[im][r] = __float_as_uint(
                        sa[(((ma * 4 + ka) * 4 + r) * 32 + lane)]);
            }
#pragma unroll
            for (int in = 0; in < 8; in++) {
                const int na = wn * 8 + in;
#pragma unroll
                for (int r = 0; r < 2; r++)
                    bf[in][r] = __float_as_uint(
                        sb[(((na * 4 + ka) * 2 + r) * 32 + lane)]);
            }
#pragma unroll
            for (int im = 0; im < 2; im++)
#pragma unroll
                for (int in = 0; in < 8; in++)
                    mma_tf32(acc[im][in], af[im], bf[in]);
        }
    };

    LDCHUNK(0);
    STCHUNK(0);
    __syncthreads();
    for (int ck = 0; ck < nchunk; ck++) {
        if (ck + 1 < nchunk) LDCHUNK(ck + 1);
        COMPUTE(ck & 1);
        if (ck + 1 < nchunk) STCHUNK((ck + 1) & 1);
        __syncthreads();
    }

    // ---- stage accumulators to smem [128][132] ----
    float* const st = (float*)(smem + 1024);
    const int g = lane >> 2, tq = lane & 3;
#pragma unroll
    for (int im = 0; im < 2; im++)
#pragma unroll
        for (int in = 0; in < 8; in++) {
            const int row = wm * 32 + im * 16 + g;
            const int col = wn * 64 + in * 8 + tq * 2;
            *(float2*)&st[row * 132 + col] =
                make_float2(acc[im][in][0], acc[im][in][1]);
            *(float2*)&st[(row + 8) * 132 + col] =
                make_float2(acc[im][in][2], acc[im][in][3]);
        }
    __syncthreads();

    if (mode == 3) {
        // out[(b*C + n)*HW + hw] = acc + bias[n] + resid[same]
        const int bimg = m0 >> 10, hw0 = m0 & 1023;
        const int hw4 = lane * 4;
#pragma unroll
        for (int j = 0; j < 16; j++) {
            const int nc = wid + 8 * j;            // tile col
            const int n = n0 + nc;
            const float bj = bias[n];
            const size_t base = ((size_t)(bimg * C_ + n)) * HW_ + hw0 + hw4;
            float4 rv = *(const float4*)(resid + base);
            float4 o;
            o.x = st[(hw4 + 0) * 132 + nc] + bj + rv.x;
            o.y = st[(hw4 + 1) * 132 + nc] + bj + rv.y;
            o.z = st[(hw4 + 2) * 132 + nc] + bj + rv.z;
            o.w = st[(hw4 + 3) * 132 + nc] + bj + rv.w;
            *(float4*)(out + base) = o;
        }
    } else {
        float4 bv = make_float4(0.f, 0.f, 0.f, 0.f);
        if (bias) bv = *(const float4*)(bias + n0 + lane * 4);
#pragma unroll 1
        for (int stp = 0; stp < 16; stp++) {
            const int rr = wid + 8 * stp;
            const int m = m0 + rr;
            if (m >= M) continue;
            float4 v = *(float4*)&st[rr * 132 + lane * 4];
            v.x += bv.x; v.y += bv.y; v.z += bv.z; v.w += bv.w;
            if (mode == 1) {
                v.x = 0.5f * v.x * (1.f + erff(v.x * 0.70710678118654752f));
                v.y = 0.5f * v.y * (1.f + erff(v.y * 0.70710678118654752f));
                v.z = 0.5f * v.z * (1.f + erff(v.z * 0.70710678118654752f));
                v.w = 0.5f * v.w * (1.f + erff(v.w * 0.70710678118654752f));
            } else if (mode == 2) {
                float4 rv = *(const float4*)(resid + (size_t)m * N + n0 + lane * 4);
                v.x += rv.x; v.y += rv.y; v.z += rv.z; v.w += rv.w;
            }
            *(float4*)(out + (size_t)m * N + n0 + lane * 4) = v;
        }
    }
}

// ---------------------------------------------------------------- GroupNorm
__global__ __launch_bounds__(256) void groupnorm_kernel(
    const float* __restrict__ x, const float* __restrict__ gam,
    const float* __restrict__ bet, float* __restrict__ out)
{
    const int b = blockIdx.x >> 5;
    const int g = blockIdx.x & 31;
    const int CPG = 16;
    const float* base = x + ((size_t)(b * C_ + g * CPG)) * HW_;
    const int tid = threadIdx.x;

    float s = 0.f, ss = 0.f;
    for (int i = tid; i < CPG * HW_; i += 256) {
        float v = base[i];
        s += v; ss += v * v;
    }
    __shared__ float red[256], red2[256];
    red[tid] = s; red2[tid] = ss;
    __syncthreads();
    for (int st = 128; st > 0; st >>= 1) {
        if (tid < st) { red[tid] += red[tid + st]; red2[tid] += red2[tid + st]; }
        __syncthreads();
    }
    __shared__ float s_mu, s_rstd;
    if (tid == 0) {
        float mu  = red[0] / (CPG * HW_);
        float var = red2[0] / (CPG * HW_) - mu * mu;
        s_mu = mu;
        s_rstd = rsqrtf(var + 1e-5f);
    }
    __shared__ float gv[16], bv[16];
    if (tid < 16) { gv[tid] = gam[g * CPG + tid]; bv[tid] = bet[g * CPG + tid]; }
    __syncthreads();
    const float mu = s_mu, rstd = s_rstd;

    __shared__ float tile[16][65];
    for (int s0 = 0; s0 < HW_; s0 += 64) {
        for (int i = tid; i < 16 * 64; i += 256) {
            int c = i >> 6, sp = i & 63;
            tile[c][sp] = base[(size_t)c * HW_ + s0 + sp];
        }
        __syncthreads();
        for (int i = tid; i < 16 * 64; i += 256) {
            int c = i & 15, sp = i >> 4;
            float v = (tile[c][sp] - mu) * rstd * gv[c] + bv[c];
            out[((size_t)(b * HW_ + s0 + sp)) * C_ + g * CPG + c] = v;
        }
        __syncthreads();
    }
}

// ---------------------------------------------------------------- LayerNorm
__global__ __launch_bounds__(256) void layernorm_kernel(
    const float* __restrict__ in, const float* __restrict__ g,
    const float* __restrict__ b, float* __restrict__ out)
{
    const int row  = blockIdx.x * 8 + (threadIdx.x >> 5);
    const int lane = threadIdx.x & 31;
    const float4* ip = (const float4*)(in + (size_t)row * D_);
    float4 v[4];
    float s = 0.f, ss = 0.f;
#pragma unroll
    for (int i = 0; i < 4; i++) {
        v[i] = ip[lane + 32 * i];
        s  += v[i].x + v[i].y + v[i].z + v[i].w;
        ss += v[i].x*v[i].x + v[i].y*v[i].y + v[i].z*v[i].z + v[i].w*v[i].w;
    }
#pragma unroll
    for (int o = 16; o > 0; o >>= 1) {
        s  += __shfl_xor_sync(0xffffffffu, s, o);
        ss += __shfl_xor_sync(0xffffffffu, ss, o);
    }
    const float mu   = s * (1.f / D_);
    const float rstd = rsqrtf(ss * (1.f / D_) - mu * mu + 1e-5f);
    const float4* gp = (const float4*)g;
    const float4* bp = (const float4*)b;
    float4* op = (float4*)(out + (size_t)row * D_);
#pragma unroll
    for (int i = 0; i < 4; i++) {
        float4 gg = gp[lane + 32 * i], bb = bp[lane + 32 * i], o4;
        o4.x = (v[i].x - mu) * rstd * gg.x + bb.x;
        o4.y = (v[i].y - mu) * rstd * gg.y + bb.y;
        o4.z = (v[i].z - mu) * rstd * gg.z + bb.z;
        o4.w = (v[i].w - mu) * rstd * gg.w + bb.w;
        op[lane + 32 * i] = o4;
    }
}

// -------------------------------------------------------- Flash attention
#define ATTN_SMEM_BYTES ((4 * 64 * 65 + 3 * 64) * (int)sizeof(float))

__global__ __launch_bounds__(256) void attn_kernel(
    const float* __restrict__ Q, const float* __restrict__ K,
    const float* __restrict__ V, float* __restrict__ O, int Lkv)
{
    extern __shared__ float sm[];
    float* Qs   = sm;
    float* Ks   = Qs + 64 * 65;
    float* Vs   = Ks + 64 * 65;
    float* Ps   = Vs + 64 * 65;
    float* mrow = Ps + 64 * 65;
    float* lrow = mrow + 64;
    float* arow = lrow + 64;

    const int q0  = blockIdx.x * 64;
    const int h   = blockIdx.y;
    const int b   = blockIdx.z;
    const int tid = threadIdx.x;
    const int tx  = tid & 15, ty = tid >> 4;
    const float scale = 0.125f;

    for (int i = tid; i < 4096; i += 256) {
        int qq = i >> 6, d = i & 63;
        Qs[qq * 65 + d] = Q[((size_t)(b * HW_ + q0 + qq)) * D_ + h * HD_ + d] * scale;
    }
    if (tid < 64) { mrow[tid] = -1e30f; lrow[tid] = 0.f; }
    float o[4][4] = {};
    __syncthreads();

    for (int j0 = 0; j0 < Lkv; j0 += 64) {
        for (int i = tid; i < 4096; i += 256) {
            int jj = i >> 6, d = i & 63;
            int j = j0 + jj;
            float kv = 0.f, vv = 0.f;
            if (j < Lkv) {
                size_t base = ((size_t)(b * Lkv + j)) * D_ + h * HD_ + d;
                kv = K[base]; vv = V[base];
            }
            Ks[jj * 65 + d] = kv;
            Vs[jj * 65 + d] = vv;
        }
        __syncthreads();

        float s[4][4] = {};
#pragma unroll 8
        for (int d = 0; d < 64; d++) {
            float a[4], bb[4];
#pragma unroll
            for (int i = 0; i < 4; i++) a[i]  = Qs[(ty * 4 + i) * 65 + d];
#pragma unroll
            for (int j = 0; j < 4; j++) bb[j] = Ks[(tx * 4 + j) * 65 + d];
#pragma unroll
            for (int i = 0; i < 4; i++)
#pragma unroll
                for (int j = 0; j < 4; j++) s[i][j] += a[i] * bb[j];
        }
#pragma unroll
        for (int i = 0; i < 4; i++)
#pragma unroll
            for (int j = 0; j < 4; j++) {
                int jg = j0 + tx * 4 + j;
                Ps[(ty * 4 + i) * 65 + tx * 4 + j] = (jg < Lkv) ? s[i][j] : -1e30f;
            }
        __syncthreads();

        {
            const int r = tid >> 2, p = tid & 3;
            float cmax = -1e30f;
            for (int jj = p; jj < 64; jj += 4)
                cmax = fmaxf(cmax, Ps[r * 65 + jj]);
            cmax = fmaxf(cmax, __shfl_xor_sync(0xffffffffu, cmax, 1));
            cmax = fmaxf(cmax, __shfl_xor_sync(0xffffffffu, cmax, 2));
            float mold = mrow[r];
            float mnew = fmaxf(mold, cmax);
            float csum = 0.f;
            for (int jj = p; jj < 64; jj += 4) {
                float e = __expf(Ps[r * 65 + jj] - mnew);
                Ps[r * 65 + jj] = e;
                csum += e;
            }
            csum += __shfl_xor_sync(0xffffffffu, csum, 1);
            csum += __shfl_xor_sync(0xffffffffu, csum, 2);
            if (p == 0) {
                float al = __expf(mold - mnew);
                arow[r] = al;
                lrow[r] = lrow[r] * al + csum;
                mrow[r] = mnew;
            }
        }
        __syncthreads();

#pragma unroll
        for (int i = 0; i < 4; i++) {
            float al = arow[ty * 4 + i];
#pragma unroll
            for (int j = 0; j < 4; j++) o[i][j] *= al;
        }
#pragma unroll 8
        for (int jj = 0; jj < 64; jj++) {
            float p[4], vv[4];
#pragma unroll
            for (int i = 0; i < 4; i++) p[i]  = Ps[(ty * 4 + i) * 65 + jj];
#pragma unroll
            for (int j = 0; j < 4; j++) vv[j] = Vs[jj * 65 + tx * 4 + j];
#pragma unroll
            for (int i = 0; i < 4; i++)
#pragma unroll
                for (int j = 0; j < 4; j++) o[i][j] += p[i] * vv[j];
        }
        __syncthreads();
    }

#pragma unroll
    for (int i = 0; i < 4; i++) {
        float inv = 1.f / lrow[ty * 4 + i];
#pragma unroll
        for (int j = 0; j < 4; j++)
            O[((size_t)(b * HW_ + q0 + ty * 4 + i)) * D_ + h * HD_ + tx * 4 + j] =
                o[i][j] * inv;
    }
}

// ------------------------------------------------------------------ driver
extern "C" void kernel_launch(void* const* d_in, const int* in_sizes, int n_in,
                              void* d_out, int out_size)
{
    const float* x         = (const float*)d_in[0];
    const float* ctx       = (const float*)d_in[1];
    const float* gn_g      = (const float*)d_in[2];
    const float* gn_b      = (const float*)d_in[3];
    const float* proj_in_w = (const float*)d_in[4];
    const float* proj_in_b = (const float*)d_in[5];
    const float* ln1_g = (const float*)d_in[6];
    const float* ln1_b = (const float*)d_in[7];
    const float* q1_w  = (const float*)d_in[8];
    const float* k1_w  = (const float*)d_in[9];
    const float* v1_w  = (const float*)d_in[10];
    const float* o1_w  = (const float*)d_in[11];
    const float* o1_b  = (const float*)d_in[12];
    const float* ln2_g = (const float*)d_in[13];
    const float* ln2_b = (const float*)d_in[14];
    const float* q2_w  = (const float*)d_in[15];
    const float* k2_w  = (const float*)d_in[16];
    const float* v2_w  = (const float*)d_in[17];
    const float* o2_w  = (const float*)d_in[18];
    const float* o2_b  = (const float*)d_in[19];
    const float* ln3_g = (const float*)d_in[20];
    const float* ln3_b = (const float*)d_in[21];
    const float* ff1_w = (const float*)d_in[22];
    const float* ff1_b = (const float*)d_in[23];
    const float* ff2_w = (const float*)d_in[24];
    const float* ff2_b = (const float*)d_in[25];
    const float* po_w  = (const float*)d_in[26];
    const float* po_b  = (const float*)d_in[27];
    float* out = (float*)d_out;

    float *pH, *pX, *pQ, *pK, *pV, *pA, *pF, *pWT;
    cudaGetSymbolAddress((void**)&pH, g_H);
    cudaGetSymbolAddress((void**)&pX, g_X);
    cudaGetSymbolAddress((void**)&pQ, g_Q);
    cudaGetSymbolAddress((void**)&pK, g_K);
    cudaGetSymbolAddress((void**)&pV, g_V);
    cudaGetSymbolAddress((void**)&pA, g_A);
    cudaGetSymbolAddress((void**)&pF, g_F);
    cudaGetSymbolAddress((void**)&pWT, g_WT);

    cudaFuncSetAttribute(attn_kernel,
                         cudaFuncAttributeMaxDynamicSharedMemorySize,
                         ATTN_SMEM_BYTES);
    cudaFuncSetAttribute(tc_gemm_kernel,
                         cudaFuncAttributeMaxDynamicSharedMemorySize,
                         GEMM_SMEM_BYTES);

    // ---- weight transposes: [K,N] -> [N,K] ----
    const dim3 tb(32, 8);
    transpose_kernel<<<dim3(D_/32, C_/32),  tb>>>(proj_in_w, pWT + OF_PIN, C_,  D_);
    transpose_kernel<<<dim3(D_/32, D_/32),  tb>>>(q1_w,  pWT + OF_Q1,  D_,  D_);
    transpose_kernel<<<dim3(D_/32, D_/32),  tb>>>(k1_w,  pWT + OF_K1,  D_,  D_);
    transpose_kernel<<<dim3(D_/32, D_/32),  tb>>>(v1_w,  pWT + OF_V1,  D_,  D_);
    transpose_kernel<<<dim3(D_/32, D_/32),  tb>>>(o1_w,  pWT + OF_O1,  D_,  D_);
    transpose_kernel<<<dim3(D_/32, D_/32),  tb>>>(q2_w,  pWT + OF_Q2,  D_,  D_);
    transpose_kernel<<<dim3(D_/32, DC_/32), tb>>>(k2_w,  pWT + OF_K2,  DC_, D_);
    transpose_kernel<<<dim3(D_/32, DC_/32), tb>>>(v2_w,  pWT + OF_V2,  DC_, D_);
    transpose_kernel<<<dim3(D_/32, D_/32),  tb>>>(o2_w,  pWT + OF_O2,  D_,  D_);
    transpose_kernel<<<dim3(FF_/32, D_/32), tb>>>(ff1_w, pWT + OF_FF1, D_,  FF_);
    transpose_kernel<<<dim3(D_/32, FF_/32), tb>>>(ff2_w, pWT + OF_FF2, FF_, D_);
    transpose_kernel<<<dim3(C_/32, D_/32),  tb>>>(po_w,  pWT + OF_PO,  D_,  C_);

    const dim3 g512(D_ / 128, M_ / 128);              // 4 x 64
    const dim3 gctx(D_ / 128, (B_ * L_ + 127) / 128); // 4 x 5
    const dim3 gff(FF_ / 128, M_ / 128);              // 16 x 64
    const dim3 gattn(HW_ / 64, NH_, B_);
    const int SB = GEMM_SMEM_BYTES;

    // GroupNorm -> X (transposed [B*HW, C])
    groupnorm_kernel<<<B_ * 32, 256>>>(x, gn_g, gn_b, pX);
    tc_gemm_kernel<<<g512, 256, SB>>>(pX, pWT + OF_PIN, proj_in_b, nullptr, pH, M_, D_, C_, 0);

    // --- self attention ---
    layernorm_kernel<<<M_ / 8, 256>>>(pH, ln1_g, ln1_b, pX);
    tc_gemm_kernel<<<g512, 256, SB>>>(pX, pWT + OF_Q1, nullptr, nullptr, pQ, M_, D_, D_, 0);
    tc_gemm_kernel<<<g512, 256, SB>>>(pX, pWT + OF_K1, nullptr, nullptr, pK, M_, D_, D_, 0);
    tc_gemm_kernel<<<g512, 256, SB>>>(pX, pWT + OF_V1, nullptr, nullptr, pV, M_, D_, D_, 0);
    attn_kernel<<<gattn, 256, ATTN_SMEM_BYTES>>>(pQ, pK, pV, pA, HW_);
    tc_gemm_kernel<<<g512, 256, SB>>>(pA, pWT + OF_O1, o1_b, pH, pH, M_, D_, D_, 2);

    // --- cross attention ---
    layernorm_kernel<<<M_ / 8, 256>>>(pH, ln2_g, ln2_b, pX);
    tc_gemm_kernel<<<g512, 256, SB>>>(pX, pWT + OF_Q2, nullptr, nullptr, pQ, M_, D_, D_, 0);
    tc_gemm_kernel<<<gctx, 256, SB>>>(ctx, pWT + OF_K2, nullptr, nullptr, pK, B_ * L_, D_, DC_, 0);
    tc_gemm_kernel<<<gctx, 256, SB>>>(ctx, pWT + OF_V2, nullptr, nullptr, pV, B_ * L_, D_, DC_, 0);
    attn_kernel<<<gattn, 256, ATTN_SMEM_BYTES>>>(pQ, pK, pV, pA, L_);
    tc_gemm_kernel<<<g512, 256, SB>>>(pA, pWT + OF_O2, o2_b, pH, pH, M_, D_, D_, 2);

    // --- feed forward ---
    layernorm_kernel<<<M_ / 8, 256>>>(pH, ln3_g, ln3_b, pX);
    tc_gemm_kernel<<<gff, 256, SB>>>(pX, pWT + OF_FF1, ff1_b, nullptr, pF, M_, FF_, D_, 1);
    tc_gemm_kernel<<<g512, 256, SB>>>(pF, pWT + OF_FF2, ff2_b, pH, pH, M_, D_, FF_, 2);

    // --- proj_out + input residual, write BCHW ---
    tc_gemm_kernel<<<g512, 256, SB>>>(pH, pWT + OF_PO, po_b, x, out, M_, D_, D_, 3);
}

// round 8
// speedup vs baseline: 2.3683x; 2.3683x over previous
#include <cuda_runtime.h>
#include <math.h>
#include <stdint.h>

// Problem constants
#define B_   8
#define C_   512
#define HW_  1024
#define D_   512
#define NH_  8
#define HD_  64
#define L_   77
#define DC_  768
#define FF_  2048
#define M_   (B_ * HW_)   // 8192 tokens

// ---------------- scratch (no allocation allowed -> __device__ globals) ----
__device__ float g_H[(size_t)M_ * D_];   // running hidden state
__device__ float g_X[(size_t)M_ * D_];   // GN / LN outputs
__device__ float g_Q[(size_t)M_ * D_];
__device__ float g_K[(size_t)M_ * D_];
__device__ float g_V[(size_t)M_ * D_];
__device__ float g_A[(size_t)M_ * D_];   // attention output
__device__ float g_F[(size_t)M_ * FF_];  // FF hidden
__device__ float g_WT[4980736];          // transposed weights [N,K]

// WT offsets
#define OF_PIN 0
#define OF_Q1  262144
#define OF_K1  524288
#define OF_V1  786432
#define OF_O1  1048576
#define OF_Q2  1310720
#define OF_K2  1572864
#define OF_V2  1966080
#define OF_O2  2359296
#define OF_FF1 2621440
#define OF_FF2 3670016
#define OF_PO  4718592

// ======================= PTX helpers =====================================
__device__ __forceinline__ uint32_t smem_u32(const void* p) {
    uint32_t a;
    asm("{ .reg .u64 t; cvta.to.shared.u64 t, %1; cvt.u32.u64 %0, t; }"
        : "=r"(a) : "l"(p));
    return a;
}

__device__ __forceinline__ void cp_async16(uint32_t dst, const void* src,
                                           int src_sz) {
    asm volatile("cp.async.cg.shared.global [%0], [%1], 16, %2;\n"
                 :: "r"(dst), "l"(src), "r"(src_sz));
}
#define CP_COMMIT() asm volatile("cp.async.commit_group;\n" ::: "memory")
#define CP_WAIT1()  asm volatile("cp.async.wait_group 1;\n" ::: "memory")
#define CP_WAIT0()  asm volatile("cp.async.wait_group 0;\n" ::: "memory")

__device__ __forceinline__ void mma_tf32(float* d, const uint32_t* a,
                                         const uint32_t* b) {
    asm volatile(
        "mma.sync.aligned.m16n8k8.row.col.f32.tf32.tf32.f32 "
        "{%0,%1,%2,%3}, {%4,%5,%6,%7}, {%8,%9}, {%0,%1,%2,%3};\n"
        : "+f"(d[0]), "+f"(d[1]), "+f"(d[2]), "+f"(d[3])
        : "r"(a[0]), "r"(a[1]), "r"(a[2]), "r"(a[3]),
          "r"(b[0]), "r"(b[1]));
}

// ======================= weight transpose [K,N] -> [N,K] ===================
__global__ __launch_bounds__(256) void transpose_kernel(
    const float* __restrict__ in, float* __restrict__ out, int K, int N)
{
    __shared__ float t[32][33];
    const int n0 = blockIdx.x * 32, k0 = blockIdx.y * 32;
    const int x = threadIdx.x, y = threadIdx.y;
#pragma unroll
    for (int i = 0; i < 32; i += 8)
        t[y + i][x] = in[(size_t)(k0 + y + i) * N + n0 + x];
    __syncthreads();
#pragma unroll
    for (int i = 0; i < 32; i += 8)
        out[(size_t)(n0 + y + i) * K + k0 + x] = t[x][y + i];
}

// ======================= tensor-core tf32 GEMM ============================
// out[M,N] = A[M,K] @ Wt[N,K]^T (+bias). Modes:
//   0: bias; 1: bias+GELU; 2: bias+resid[M,N]; 3: BCHW out + bias + resid
// CTA 128x128, 8 warps (4m x 2n), warp tile 32x64, K chunk 32.
// Smem: row-major 128 rows x 32 floats (128B), 16B-group swizzle:
//   word(row, col) = row*32 + ((col>>2) ^ (row&7))*4 + (col&3)
// cp.async double buffer; fragments read via conflict-free lds.32.
#define GEMM_SMEM_BYTES 68608
#define A0OFS 0
#define B0OFS 4096
#define A1OFS 8192
#define B1OFS 12288

__global__ __launch_bounds__(256) void tc_gemm_kernel(
    const float* __restrict__ A, const float* __restrict__ Wt,
    const float* __restrict__ bias, const float* __restrict__ resid,
    float* __restrict__ out, int M, int N, int K, int mode)
{
    extern __shared__ char smem[];
    float* const smemf = (float*)smem;
    const uint32_t sb = smem_u32(smem);

    const int tid  = threadIdx.x;
    const int wid  = tid >> 5, lane = tid & 31;
    const int c8   = tid & 7,  r8   = tid >> 3;     // fill mapping
    const int m0   = blockIdx.y * 128;
    const int n0   = blockIdx.x * 128;
    const int wm   = wid >> 1, wn = wid & 1;        // 4 x 2 warps
    const int lq   = lane >> 2, lr = lane & 3;
    const int nchunk = K >> 5;

    float acc[2][8][4];
#pragma unroll
    for (int i = 0; i < 2; i++)
#pragma unroll
        for (int j = 0; j < 8; j++)
#pragma unroll
            for (int r = 0; r < 4; r++) acc[i][j][r] = 0.f;

    // ---- issue cp.async fills for one chunk ----
    auto ISSUE = [&](int ck, int bsel) {
        const int k0 = ck << 5;
        const uint32_t aofs = bsel ? A1OFS : A0OFS;
        const uint32_t bofs = bsel ? B1OFS : B0OFS;
#pragma unroll
        for (int i = 0; i < 4; i++) {
            const int row = r8 + 32 * i;
            const uint32_t w = (uint32_t)(row * 32 + ((c8 ^ (row & 7)) * 4));
            const int m = m0 + row;
            cp_async16(sb + (aofs + w) * 4,
                       A + (size_t)m * K + k0 + c8 * 4, (m < M) ? 16 : 0);
            cp_async16(sb + (bofs + w) * 4,
                       Wt + (size_t)(n0 + row) * K + k0 + c8 * 4, 16);
        }
    };
    // ---- compute one chunk from smem ----
    auto COMPUTE = [&](int bsel) {
        const float* const sa = smemf + (bsel ? A1OFS : A0OFS);
        const float* const sbp = smemf + (bsel ? B1OFS : B0OFS);
#pragma unroll
        for (int ka = 0; ka < 4; ka++) {
            uint32_t af[2][4], bf[8][2];
#pragma unroll
            for (int im = 0; im < 2; im++) {
                const int mr = wm * 32 + im * 16 + lq;
                const int g0 = ((2 * ka) ^ (mr & 7)) * 4 + lr;
                const int g1 = ((2 * ka + 1) ^ (mr & 7)) * 4 + lr;
                af[im][0] = __float_as_uint(sa[mr * 32 + g0]);
                af[im][1] = __float_as_uint(sa[(mr + 8) * 32 + g0]);
                af[im][2] = __float_as_uint(sa[mr * 32 + g1]);
                af[im][3] = __float_as_uint(sa[(mr + 8) * 32 + g1]);
            }
#pragma unroll
            for (int in = 0; in < 8; in++) {
                const int nr = wn * 64 + in * 8 + lq;
                const int g0 = ((2 * ka) ^ (nr & 7)) * 4 + lr;
                const int g1 = ((2 * ka + 1) ^ (nr & 7)) * 4 + lr;
                bf[in][0] = __float_as_uint(sbp[nr * 32 + g0]);
                bf[in][1] = __float_as_uint(sbp[nr * 32 + g1]);
            }
#pragma unroll
            for (int im = 0; im < 2; im++)
#pragma unroll
                for (int in = 0; in < 8; in++)
                    mma_tf32(acc[im][in], af[im], bf[in]);
        }
    };

    ISSUE(0, 0); CP_COMMIT();
    if (nchunk > 1) ISSUE(1, 1);
    CP_COMMIT();
    for (int ck = 0; ck < nchunk; ck++) {
        if (ck + 1 < nchunk) CP_WAIT1(); else CP_WAIT0();
        __syncthreads();
        COMPUTE(ck & 1);
        __syncthreads();
        if (ck + 2 < nchunk) { ISSUE(ck + 2, ck & 1); CP_COMMIT(); }
    }

    // ---- stage accumulators to smem [128][132] ----
    float* const st = smemf;
    const int tq = lane & 3;
#pragma unroll
    for (int im = 0; im < 2; im++)
#pragma unroll
        for (int in = 0; in < 8; in++) {
            const int row = wm * 32 + im * 16 + lq;
            const int col = wn * 64 + in * 8 + tq * 2;
            *(float2*)&st[row * 132 + col] =
                make_float2(acc[im][in][0], acc[im][in][1]);
            *(float2*)&st[(row + 8) * 132 + col] =
                make_float2(acc[im][in][2], acc[im][in][3]);
        }
    __syncthreads();

    if (mode == 3) {
        // out[(b*C + n)*HW + hw] = acc + bias[n] + resid[same]
        const int bimg = m0 >> 10, hw0 = m0 & 1023;
        const int hw4 = lane * 4;
#pragma unroll
        for (int j = 0; j < 16; j++) {
            const int nc = wid + 8 * j;            // tile col
            const int n = n0 + nc;
            const float bj = bias[n];
            const size_t base = ((size_t)(bimg * C_ + n)) * HW_ + hw0 + hw4;
            float4 rv = *(const float4*)(resid + base);
            float4 o;
            o.x = st[(hw4 + 0) * 132 + nc] + bj + rv.x;
            o.y = st[(hw4 + 1) * 132 + nc] + bj + rv.y;
            o.z = st[(hw4 + 2) * 132 + nc] + bj + rv.z;
            o.w = st[(hw4 + 3) * 132 + nc] + bj + rv.w;
            *(float4*)(out + base) = o;
        }
    } else {
        float4 bv = make_float4(0.f, 0.f, 0.f, 0.f);
        if (bias) bv = *(const float4*)(bias + n0 + lane * 4);
#pragma unroll 1
        for (int stp = 0; stp < 16; stp++) {
            const int rr = wid + 8 * stp;
            const int m = m0 + rr;
            if (m >= M) continue;
            float4 v = *(float4*)&st[rr * 132 + lane * 4];
            v.x += bv.x; v.y += bv.y; v.z += bv.z; v.w += bv.w;
            if (mode == 1) {
                v.x = 0.5f * v.x * (1.f + erff(v.x * 0.70710678118654752f));
                v.y = 0.5f * v.y * (1.f + erff(v.y * 0.70710678118654752f));
                v.z = 0.5f * v.z * (1.f + erff(v.z * 0.70710678118654752f));
                v.w = 0.5f * v.w * (1.f + erff(v.w * 0.70710678118654752f));
            } else if (mode == 2) {
                float4 rv = *(const float4*)(resid + (size_t)m * N + n0 + lane * 4);
                v.x += rv.x; v.y += rv.y; v.z += rv.z; v.w += rv.w;
            }
            *(float4*)(out + (size_t)m * N + n0 + lane * 4) = v;
        }
    }
}

// ---------------------------------------------------------------- GroupNorm
__global__ __launch_bounds__(256) void groupnorm_kernel(
    const float* __restrict__ x, const float* __restrict__ gam,
    const float* __restrict__ bet, float* __restrict__ out)
{
    const int b = blockIdx.x >> 5;
    const int g = blockIdx.x & 31;
    const int CPG = 16;
    const float* base = x + ((size_t)(b * C_ + g * CPG)) * HW_;
    const int tid = threadIdx.x;

    float s = 0.f, ss = 0.f;
    for (int i = tid; i < CPG * HW_; i += 256) {
        float v = base[i];
        s += v; ss += v * v;
    }
    __shared__ float red[256], red2[256];
    red[tid] = s; red2[tid] = ss;
    __syncthreads();
    for (int st = 128; st > 0; st >>= 1) {
        if (tid < st) { red[tid] += red[tid + st]; red2[tid] += red2[tid + st]; }
        __syncthreads();
    }
    __shared__ float s_mu, s_rstd;
    if (tid == 0) {
        float mu  = red[0] / (CPG * HW_);
        float var = red2[0] / (CPG * HW_) - mu * mu;
        s_mu = mu;
        s_rstd = rsqrtf(var + 1e-5f);
    }
    __shared__ float gv[16], bv[16];
    if (tid < 16) { gv[tid] = gam[g * CPG + tid]; bv[tid] = bet[g * CPG + tid]; }
    __syncthreads();
    const float mu = s_mu, rstd = s_rstd;

    __shared__ float tile[16][65];
    for (int s0 = 0; s0 < HW_; s0 += 64) {
        for (int i = tid; i < 16 * 64; i += 256) {
            int c = i >> 6, sp = i & 63;
            tile[c][sp] = base[(size_t)c * HW_ + s0 + sp];
        }
        __syncthreads();
        for (int i = tid; i < 16 * 64; i += 256) {
            int c = i & 15, sp = i >> 4;
            float v = (tile[c][sp] - mu) * rstd * gv[c] + bv[c];
            out[((size_t)(b * HW_ + s0 + sp)) * C_ + g * CPG + c] = v;
        }
        __syncthreads();
    }
}

// ---------------------------------------------------------------- LayerNorm
__global__ __launch_bounds__(256) void layernorm_kernel(
    const float* __restrict__ in, const float* __restrict__ g,
    const float* __restrict__ b, float* __restrict__ out)
{
    const int row  = blockIdx.x * 8 + (threadIdx.x >> 5);
    const int lane = threadIdx.x & 31;
    const float4* ip = (const float4*)(in + (size_t)row * D_);
    float4 v[4];
    float s = 0.f, ss = 0.f;
#pragma unroll
    for (int i = 0; i < 4; i++) {
        v[i] = ip[lane + 32 * i];
        s  += v[i].x + v[i].y + v[i].z + v[i].w;
        ss += v[i].x*v[i].x + v[i].y*v[i].y + v[i].z*v[i].z + v[i].w*v[i].w;
    }
#pragma unroll
    for (int o = 16; o > 0; o >>= 1) {
        s  += __shfl_xor_sync(0xffffffffu, s, o);
        ss += __shfl_xor_sync(0xffffffffu, ss, o);
    }
    const float mu   = s * (1.f / D_);
    const float rstd = rsqrtf(ss * (1.f / D_) - mu * mu + 1e-5f);
    const float4* gp = (const float4*)g;
    const float4* bp = (const float4*)b;
    float4* op = (float4*)(out + (size_t)row * D_);
#pragma unroll
    for (int i = 0; i < 4; i++) {
        float4 gg = gp[lane + 32 * i], bb = bp[lane + 32 * i], o4;
        o4.x = (v[i].x - mu) * rstd * gg.x + bb.x;
        o4.y = (v[i].y - mu) * rstd * gg.y + bb.y;
        o4.z = (v[i].z - mu) * rstd * gg.z + bb.z;
        o4.w = (v[i].w - mu) * rstd * gg.w + bb.w;
        op[lane + 32 * i] = o4;
    }
}

// -------------------------------------------------------- Flash attention
#define ATTN_SMEM_BYTES ((4 * 64 * 65 + 3 * 64) * (int)sizeof(float))

__global__ __launch_bounds__(256) void attn_kernel(
    const float* __restrict__ Q, const float* __restrict__ K,
    const float* __restrict__ V, float* __restrict__ O, int Lkv)
{
    extern __shared__ float sm[];
    float* Qs   = sm;
    float* Ks   = Qs + 64 * 65;
    float* Vs   = Ks + 64 * 65;
    float* Ps   = Vs + 64 * 65;
    float* mrow = Ps + 64 * 65;
    float* lrow = mrow + 64;
    float* arow = lrow + 64;

    const int q0  = blockIdx.x * 64;
    const int h   = blockIdx.y;
    const int b   = blockIdx.z;
    const int tid = threadIdx.x;
    const int tx  = tid & 15, ty = tid >> 4;
    const float scale = 0.125f;

    for (int i = tid; i < 4096; i += 256) {
        int qq = i >> 6, d = i & 63;
        Qs[qq * 65 + d] = Q[((size_t)(b * HW_ + q0 + qq)) * D_ + h * HD_ + d] * scale;
    }
    if (tid < 64) { mrow[tid] = -1e30f; lrow[tid] = 0.f; }
    float o[4][4] = {};
    __syncthreads();

    for (int j0 = 0; j0 < Lkv; j0 += 64) {
        for (int i = tid; i < 4096; i += 256) {
            int jj = i >> 6, d = i & 63;
            int j = j0 + jj;
            float kv = 0.f, vv = 0.f;
            if (j < Lkv) {
                size_t base = ((size_t)(b * Lkv + j)) * D_ + h * HD_ + d;
                kv = K[base]; vv = V[base];
            }
            Ks[jj * 65 + d] = kv;
            Vs[jj * 65 + d] = vv;
        }
        __syncthreads();

        float s[4][4] = {};
#pragma unroll 8
        for (int d = 0; d < 64; d++) {
            float a[4], bb[4];
#pragma unroll
            for (int i = 0; i < 4; i++) a[i]  = Qs[(ty * 4 + i) * 65 + d];
#pragma unroll
            for (int j = 0; j < 4; j++) bb[j] = Ks[(tx * 4 + j) * 65 + d];
#pragma unroll
            for (int i = 0; i < 4; i++)
#pragma unroll
                for (int j = 0; j < 4; j++) s[i][j] += a[i] * bb[j];
        }
#pragma unroll
        for (int i = 0; i < 4; i++)
#pragma unroll
            for (int j = 0; j < 4; j++) {
                int jg = j0 + tx * 4 + j;
                Ps[(ty * 4 + i) * 65 + tx * 4 + j] = (jg < Lkv) ? s[i][j] : -1e30f;
            }
        __syncthreads();

        {
            const int r = tid >> 2, p = tid & 3;
            float cmax = -1e30f;
            for (int jj = p; jj < 64; jj += 4)
                cmax = fmaxf(cmax, Ps[r * 65 + jj]);
            cmax = fmaxf(cmax, __shfl_xor_sync(0xffffffffu, cmax, 1));
            cmax = fmaxf(cmax, __shfl_xor_sync(0xffffffffu, cmax, 2));
            float mold = mrow[r];
            float mnew = fmaxf(mold, cmax);
            float csum = 0.f;
            for (int jj = p; jj < 64; jj += 4) {
                float e = __expf(Ps[r * 65 + jj] - mnew);
                Ps[r * 65 + jj] = e;
                csum += e;
            }
            csum += __shfl_xor_sync(0xffffffffu, csum, 1);
            csum += __shfl_xor_sync(0xffffffffu, csum, 2);
            if (p == 0) {
                float al = __expf(mold - mnew);
                arow[r] = al;
                lrow[r] = lrow[r] * al + csum;
                mrow[r] = mnew;
            }
        }
        __syncthreads();

#pragma unroll
        for (int i = 0; i < 4; i++) {
            float al = arow[ty * 4 + i];
#pragma unroll
            for (int j = 0; j < 4; j++) o[i][j] *= al;
        }
#pragma unroll 8
        for (int jj = 0; jj < 64; jj++) {
            float p[4], vv[4];
#pragma unroll
            for (int i = 0; i < 4; i++) p[i]  = Ps[(ty * 4 + i) * 65 + jj];
#pragma unroll
            for (int j = 0; j < 4; j++) vv[j] = Vs[jj * 65 + tx * 4 + j];
#pragma unroll
            for (int i = 0; i < 4; i++)
#pragma unroll
                for (int j = 0; j < 4; j++) o[i][j] += p[i] * vv[j];
        }
        __syncthreads();
    }

#pragma unroll
    for (int i = 0; i < 4; i++) {
        float inv = 1.f / lrow[ty * 4 + i];
#pragma unroll
        for (int j = 0; j < 4; j++)
            O[((size_t)(b * HW_ + q0 + ty * 4 + i)) * D_ + h * HD_ + tx * 4 + j] =
                o[i][j] * inv;
    }
}

// ------------------------------------------------------------------ driver
extern "C" void kernel_launch(void* const* d_in, const int* in_sizes, int n_in,
                              void* d_out, int out_size)
{
    const float* x         = (const float*)d_in[0];
    const float* ctx       = (const float*)d_in[1];
    const float* gn_g      = (const float*)d_in[2];
    const float* gn_b      = (const float*)d_in[3];
    const float* proj_in_w = (const float*)d_in[4];
    const float* proj_in_b = (const float*)d_in[5];
    const float* ln1_g = (const float*)d_in[6];
    const float* ln1_b = (const float*)d_in[7];
    const float* q1_w  = (const float*)d_in[8];
    const float* k1_w  = (const float*)d_in[9];
    const float* v1_w  = (const float*)d_in[10];
    const float* o1_w  = (const float*)d_in[11];
    const float* o1_b  = (const float*)d_in[12];
    const float* ln2_g = (const float*)d_in[13];
    const float* ln2_b = (const float*)d_in[14];
    const float* q2_w  = (const float*)d_in[15];
    const float* k2_w  = (const float*)d_in[16];
    const float* v2_w  = (const float*)d_in[17];
    const float* o2_w  = (const float*)d_in[18];
    const float* o2_b  = (const float*)d_in[19];
    const float* ln3_g = (const float*)d_in[20];
    const float* ln3_b = (const float*)d_in[21];
    const float* ff1_w = (const float*)d_in[22];
    const float* ff1_b = (const float*)d_in[23];
    const float* ff2_w = (const float*)d_in[24];
    const float* ff2_b = (const float*)d_in[25];
    const float* po_w  = (const float*)d_in[26];
    const float* po_b  = (const float*)d_in[27];
    float* out = (float*)d_out;

    float *pH, *pX, *pQ, *pK, *pV, *pA, *pF, *pWT;
    cudaGetSymbolAddress((void**)&pH, g_H);
    cudaGetSymbolAddress((void**)&pX, g_X);
    cudaGetSymbolAddress((void**)&pQ, g_Q);
    cudaGetSymbolAddress((void**)&pK, g_K);
    cudaGetSymbolAddress((void**)&pV, g_V);
    cudaGetSymbolAddress((void**)&pA, g_A);
    cudaGetSymbolAddress((void**)&pF, g_F);
    cudaGetSymbolAddress((void**)&pWT, g_WT);

    cudaFuncSetAttribute(attn_kernel,
                         cudaFuncAttributeMaxDynamicSharedMemorySize,
                         ATTN_SMEM_BYTES);
    cudaFuncSetAttribute(tc_gemm_kernel,
                         cudaFuncAttributeMaxDynamicSharedMemorySize,
                         GEMM_SMEM_BYTES);

    const dim3 tb(32, 8);
    const dim3 g512(D_ / 128, M_ / 128);              // 4 x 64
    const dim3 gctx(D_ / 128, (B_ * L_ + 127) / 128); // 4 x 5
    const dim3 gff(FF_ / 128, M_ / 128);              // 16 x 64
    const dim3 gattn(HW_ / 64, NH_, B_);
    const int SB = GEMM_SMEM_BYTES;

    // Launch order arranged so ncu (-s 5 -c 1) profiles the proj_in GEMM.
    groupnorm_kernel<<<B_ * 32, 256>>>(x, gn_g, gn_b, pX);                      // 1
    transpose_kernel<<<dim3(D_/32, C_/32),  tb>>>(proj_in_w, pWT + OF_PIN, C_, D_); // 2
    transpose_kernel<<<dim3(D_/32, D_/32),  tb>>>(q1_w,  pWT + OF_Q1,  D_,  D_);    // 3
    transpose_kernel<<<dim3(D_/32, D_/32),  tb>>>(k1_w,  pWT + OF_K1,  D_,  D_);    // 4
    transpose_kernel<<<dim3(D_/32, D_/32),  tb>>>(v1_w,  pWT + OF_V1,  D_,  D_);    // 5
    tc_gemm_kernel<<<g512, 256, SB>>>(pX, pWT + OF_PIN, proj_in_b, nullptr,
                                      pH, M_, D_, C_, 0);                       // 6 (profiled)
    transpose_kernel<<<dim3(D_/32, D_/32),  tb>>>(o1_w,  pWT + OF_O1,  D_,  D_);
    transpose_kernel<<<dim3(D_/32, D_/32),  tb>>>(q2_w,  pWT + OF_Q2,  D_,  D_);
    transpose_kernel<<<dim3(D_/32, DC_/32), tb>>>(k2_w,  pWT + OF_K2,  DC_, D_);
    transpose_kernel<<<dim3(D_/32, DC_/32), tb>>>(v2_w,  pWT + OF_V2,  DC_, D_);
    transpose_kernel<<<dim3(D_/32, D_/32),  tb>>>(o2_w,  pWT + OF_O2,  D_,  D_);
    transpose_kernel<<<dim3(FF_/32, D_/32), tb>>>(ff1_w, pWT + OF_FF1, D_,  FF_);
    transpose_kernel<<<dim3(D_/32, FF_/32), tb>>>(ff2_w, pWT + OF_FF2, FF_, D_);
    transpose_kernel<<<dim3(C_/32, D_/32),  tb>>>(po_w,  pWT + OF_PO,  D_,  C_);

    // --- self attention ---
    layernorm_kernel<<<M_ / 8, 256>>>(pH, ln1_g, ln1_b, pX);
    tc_gemm_kernel<<<g512, 256, SB>>>(pX, pWT + OF_Q1, nullptr, nullptr, pQ, M_, D_, D_, 0);
    tc_gemm_kernel<<<g512, 256, SB>>>(pX, pWT + OF_K1, nullptr, nullptr, pK, M_, D_, D_, 0);
    tc_gemm_kernel<<<g512, 256, SB>>>(pX, pWT + OF_V1, nullptr, nullptr, pV, M_, D_, D_, 0);
    attn_kernel<<<gattn, 256, ATTN_SMEM_BYTES>>>(pQ, pK, pV, pA, HW_);
    tc_gemm_kernel<<<g512, 256, SB>>>(pA, pWT + OF_O1, o1_b, pH, pH, M_, D_, D_, 2);

    // --- cross attention ---
    layernorm_kernel<<<M_ / 8, 256>>>(pH, ln2_g, ln2_b, pX);
    tc_gemm_kernel<<<g512, 256, SB>>>(pX, pWT + OF_Q2, nullptr, nullptr, pQ, M_, D_, D_, 0);
    tc_gemm_kernel<<<gctx, 256, SB>>>(ctx, pWT + OF_K2, nullptr, nullptr, pK, B_ * L_, D_, DC_, 0);
    tc_gemm_kernel<<<gctx, 256, SB>>>(ctx, pWT + OF_V2, nullptr, nullptr, pV, B_ * L_, D_, DC_, 0);
    attn_kernel<<<gattn, 256, ATTN_SMEM_BYTES>>>(pQ, pK, pV, pA, L_);
    tc_gemm_kernel<<<g512, 256, SB>>>(pA, pWT + OF_O2, o2_b, pH, pH, M_, D_, D_, 2);

    // --- feed forward ---
    layernorm_kernel<<<M_ / 8, 256>>>(pH, ln3_g, ln3_b, pX);
    tc_gemm_kernel<<<gff, 256, SB>>>(pX, pWT + OF_FF1, ff1_b, nullptr, pF, M_, FF_, D_, 1);
    tc_gemm_kernel<<<g512, 256, SB>>>(pF, pWT + OF_FF2, ff2_b, pH, pH, M_, D_, FF_, 2);

    // --- proj_out + input residual, write BCHW ---
    tc_gemm_kernel<<<g512, 256, SB>>>(pH, pWT + OF_PO, po_b, x, out, M_, D_, D_, 3);
}

// round 9
// speedup vs baseline: 2.3707x; 1.0010x over previous
#include <cuda_runtime.h>
#include <math.h>
#include <stdint.h>

// Problem constants
#define B_   8
#define C_   512
#define HW_  1024
#define D_   512
#define NH_  8
#define HD_  64
#define L_   77
#define DC_  768
#define FF_  2048
#define M_   (B_ * HW_)   // 8192 tokens

// ---------------- scratch (no allocation allowed -> __device__ globals) ----
__device__ float g_H[(size_t)M_ * D_];   // running hidden state
__device__ float g_X[(size_t)M_ * D_];   // GN / LN outputs
__device__ float g_Q[(size_t)M_ * D_];
__device__ float g_K[(size_t)M_ * D_];
__device__ float g_V[(size_t)M_ * D_];
__device__ float g_A[(size_t)M_ * D_];   // attention output
__device__ float g_F[(size_t)M_ * FF_];  // FF hidden
__device__ float g_WT[4980736];          // transposed weights [N,K]

// WT offsets
#define OF_PIN 0
#define OF_Q1  262144
#define OF_K1  524288
#define OF_V1  786432
#define OF_O1  1048576
#define OF_Q2  1310720
#define OF_K2  1572864
#define OF_V2  1966080
#define OF_O2  2359296
#define OF_FF1 2621440
#define OF_FF2 3670016
#define OF_PO  4718592

// ======================= PTX helpers =====================================
__device__ __forceinline__ uint32_t smem_u32(const void* p) {
    uint32_t a;
    asm("{ .reg .u64 t; cvta.to.shared.u64 t, %1; cvt.u32.u64 %0, t; }"
        : "=r"(a) : "l"(p));
    return a;
}

__device__ __forceinline__ void cp_async16(uint32_t dst, const void* src,
                                           int src_sz) {
    asm volatile("cp.async.cg.shared.global [%0], [%1], 16, %2;\n"
                 :: "r"(dst), "l"(src), "r"(src_sz));
}
#define CP_COMMIT() asm volatile("cp.async.commit_group;\n" ::: "memory")
#define CP_WAIT1()  asm volatile("cp.async.wait_group 1;\n" ::: "memory")
#define CP_WAIT0()  asm volatile("cp.async.wait_group 0;\n" ::: "memory")

__device__ __forceinline__ uint32_t f2tf32(float f) {
    uint32_t o;
    asm("cvt.rna.tf32.f32 %0, %1;" : "=r"(o) : "f"(f));
    return o;
}

__device__ __forceinline__ void mma_tf32(float* d, const uint32_t* a,
                                         const uint32_t* b) {
    asm volatile(
        "mma.sync.aligned.m16n8k8.row.col.f32.tf32.tf32.f32 "
        "{%0,%1,%2,%3}, {%4,%5,%6,%7}, {%8,%9}, {%0,%1,%2,%3};\n"
        : "+f"(d[0]), "+f"(d[1]), "+f"(d[2]), "+f"(d[3])
        : "r"(a[0]), "r"(a[1]), "r"(a[2]), "r"(a[3]),
          "r"(b[0]), "r"(b[1]));
}

// ======================= weight transpose [K,N] -> [N,K] ===================
// Also pre-rounds weights to tf32 (RNA) so GEMM B-operand truncation is exact.
__global__ __launch_bounds__(256) void transpose_kernel(
    const float* __restrict__ in, float* __restrict__ out, int K, int N)
{
    __shared__ float t[32][33];
    const int n0 = blockIdx.x * 32, k0 = blockIdx.y * 32;
    const int x = threadIdx.x, y = threadIdx.y;
#pragma unroll
    for (int i = 0; i < 32; i += 8)
        t[y + i][x] = in[(size_t)(k0 + y + i) * N + n0 + x];
    __syncthreads();
#pragma unroll
    for (int i = 0; i < 32; i += 8)
        out[(size_t)(n0 + y + i) * K + k0 + x] =
            __uint_as_float(f2tf32(t[x][y + i]));
}

// ======================= tensor-core tf32 GEMM ============================
// out[M,N] = A[M,K] @ Wt[N,K]^T (+bias). Modes:
//   0: bias; 1: bias+GELU; 2: bias+resid[M,N]; 3: BCHW out + bias + resid
#define GEMM_SMEM_BYTES 68608
#define A0OFS 0
#define B0OFS 4096
#define A1OFS 8192
#define B1OFS 12288

__global__ __launch_bounds__(256) void tc_gemm_kernel(
    const float* __restrict__ A, const float* __restrict__ Wt,
    const float* __restrict__ bias, const float* __restrict__ resid,
    float* __restrict__ out, int M, int N, int K, int mode)
{
    extern __shared__ char smem[];
    float* const smemf = (float*)smem;
    const uint32_t sb = smem_u32(smem);

    const int tid  = threadIdx.x;
    const int wid  = tid >> 5, lane = tid & 31;
    const int c8   = tid & 7,  r8   = tid >> 3;
    const int m0   = blockIdx.y * 128;
    const int n0   = blockIdx.x * 128;
    const int wm   = wid >> 1, wn = wid & 1;
    const int lq   = lane >> 2, lr = lane & 3;
    const int nchunk = K >> 5;

    float acc[2][8][4];
#pragma unroll
    for (int i = 0; i < 2; i++)
#pragma unroll
        for (int j = 0; j < 8; j++)
#pragma unroll
            for (int r = 0; r < 4; r++) acc[i][j][r] = 0.f;

    auto ISSUE = [&](int ck, int bsel) {
        const int k0 = ck << 5;
        const uint32_t aofs = bsel ? A1OFS : A0OFS;
        const uint32_t bofs = bsel ? B1OFS : B0OFS;
#pragma unroll
        for (int i = 0; i < 4; i++) {
            const int row = r8 + 32 * i;
            const uint32_t w = (uint32_t)(row * 32 + ((c8 ^ (row & 7)) * 4));
            const int m = m0 + row;
            cp_async16(sb + (aofs + w) * 4,
                       A + (size_t)m * K + k0 + c8 * 4, (m < M) ? 16 : 0);
            cp_async16(sb + (bofs + w) * 4,
                       Wt + (size_t)(n0 + row) * K + k0 + c8 * 4, 16);
        }
    };
    auto COMPUTE = [&](int bsel) {
        const float* const sa = smemf + (bsel ? A1OFS : A0OFS);
        const float* const sbp = smemf + (bsel ? B1OFS : B0OFS);
#pragma unroll
        for (int ka = 0; ka < 4; ka++) {
            uint32_t af[2][4], bf[8][2];
#pragma unroll
            for (int im = 0; im < 2; im++) {
                const int mr = wm * 32 + im * 16 + lq;
                const int g0 = ((2 * ka) ^ (mr & 7)) * 4 + lr;
                const int g1 = ((2 * ka + 1) ^ (mr & 7)) * 4 + lr;
                af[im][0] = __float_as_uint(sa[mr * 32 + g0]);
                af[im][1] = __float_as_uint(sa[(mr + 8) * 32 + g0]);
                af[im][2] = __float_as_uint(sa[mr * 32 + g1]);
                af[im][3] = __float_as_uint(sa[(mr + 8) * 32 + g1]);
            }
#pragma unroll
            for (int in = 0; in < 8; in++) {
                const int nr = wn * 64 + in * 8 + lq;
                const int g0 = ((2 * ka) ^ (nr & 7)) * 4 + lr;
                const int g1 = ((2 * ka + 1) ^ (nr & 7)) * 4 + lr;
                bf[in][0] = __float_as_uint(sbp[nr * 32 + g0]);
                bf[in][1] = __float_as_uint(sbp[nr * 32 + g1]);
            }
#pragma unroll
            for (int im = 0; im < 2; im++)
#pragma unroll
                for (int in = 0; in < 8; in++)
                    mma_tf32(acc[im][in], af[im], bf[in]);
        }
    };

    ISSUE(0, 0); CP_COMMIT();
    if (nchunk > 1) ISSUE(1, 1);
    CP_COMMIT();
    for (int ck = 0; ck < nchunk; ck++) {
        if (ck + 1 < nchunk) CP_WAIT1(); else CP_WAIT0();
        __syncthreads();
        COMPUTE(ck & 1);
        __syncthreads();
        if (ck + 2 < nchunk) { ISSUE(ck + 2, ck & 1); CP_COMMIT(); }
    }

    float* const st = smemf;
    const int tq = lane & 3;
#pragma unroll
    for (int im = 0; im < 2; im++)
#pragma unroll
        for (int in = 0; in < 8; in++) {
            const int row = wm * 32 + im * 16 + lq;
            const int col = wn * 64 + in * 8 + tq * 2;
            *(float2*)&st[row * 132 + col] =
                make_float2(acc[im][in][0], acc[im][in][1]);
            *(float2*)&st[(row + 8) * 132 + col] =
                make_float2(acc[im][in][2], acc[im][in][3]);
        }
    __syncthreads();

    if (mode == 3) {
        const int bimg = m0 >> 10, hw0 = m0 & 1023;
        const int hw4 = lane * 4;
#pragma unroll
        for (int j = 0; j < 16; j++) {
            const int nc = wid + 8 * j;
            const int n = n0 + nc;
            const float bj = bias[n];
            const size_t base = ((size_t)(bimg * C_ + n)) * HW_ + hw0 + hw4;
            float4 rv = *(const float4*)(resid + base);
            float4 o;
            o.x = st[(hw4 + 0) * 132 + nc] + bj + rv.x;
            o.y = st[(hw4 + 1) * 132 + nc] + bj + rv.y;
            o.z = st[(hw4 + 2) * 132 + nc] + bj + rv.z;
            o.w = st[(hw4 + 3) * 132 + nc] + bj + rv.w;
            *(float4*)(out + base) = o;
        }
    } else {
        float4 bv = make_float4(0.f, 0.f, 0.f, 0.f);
        if (bias) bv = *(const float4*)(bias + n0 + lane * 4);
#pragma unroll 1
        for (int stp = 0; stp < 16; stp++) {
            const int rr = wid + 8 * stp;
            const int m = m0 + rr;
            if (m >= M) continue;
            float4 v = *(float4*)&st[rr * 132 + lane * 4];
            v.x += bv.x; v.y += bv.y; v.z += bv.z; v.w += bv.w;
            if (mode == 1) {
                v.x = 0.5f * v.x * (1.f + erff(v.x * 0.70710678118654752f));
                v.y = 0.5f * v.y * (1.f + erff(v.y * 0.70710678118654752f));
                v.z = 0.5f * v.z * (1.f + erff(v.z * 0.70710678118654752f));
                v.w = 0.5f * v.w * (1.f + erff(v.w * 0.70710678118654752f));
            } else if (mode == 2) {
                float4 rv = *(const float4*)(resid + (size_t)m * N + n0 + lane * 4);
                v.x += rv.x; v.y += rv.y; v.z += rv.z; v.w += rv.w;
            }
            *(float4*)(out + (size_t)m * N + n0 + lane * 4) = v;
        }
    }
}

// ---------------------------------------------------------------- GroupNorm
__global__ __launch_bounds__(256) void groupnorm_kernel(
    const float* __restrict__ x, const float* __restrict__ gam,
    const float* __restrict__ bet, float* __restrict__ out)
{
    const int b = blockIdx.x >> 5;
    const int g = blockIdx.x & 31;
    const int CPG = 16;
    const float* base = x + ((size_t)(b * C_ + g * CPG)) * HW_;
    const int tid = threadIdx.x;

    float s = 0.f, ss = 0.f;
    for (int i = tid; i < CPG * HW_; i += 256) {
        float v = base[i];
        s += v; ss += v * v;
    }
    __shared__ float red[256], red2[256];
    red[tid] = s; red2[tid] = ss;
    __syncthreads();
    for (int st = 128; st > 0; st >>= 1) {
        if (tid < st) { red[tid] += red[tid + st]; red2[tid] += red2[tid + st]; }
        __syncthreads();
    }
    __shared__ float s_mu, s_rstd;
    if (tid == 0) {
        float mu  = red[0] / (CPG * HW_);
        float var = red2[0] / (CPG * HW_) - mu * mu;
        s_mu = mu;
        s_rstd = rsqrtf(var + 1e-5f);
    }
    __shared__ float gv[16], bv[16];
    if (tid < 16) { gv[tid] = gam[g * CPG + tid]; bv[tid] = bet[g * CPG + tid]; }
    __syncthreads();
    const float mu = s_mu, rstd = s_rstd;

    __shared__ float tile[16][65];
    for (int s0 = 0; s0 < HW_; s0 += 64) {
        for (int i = tid; i < 16 * 64; i += 256) {
            int c = i >> 6, sp = i & 63;
            tile[c][sp] = base[(size_t)c * HW_ + s0 + sp];
        }
        __syncthreads();
        for (int i = tid; i < 16 * 64; i += 256) {
            int c = i & 15, sp = i >> 4;
            float v = (tile[c][sp] - mu) * rstd * gv[c] + bv[c];
            out[((size_t)(b * HW_ + s0 + sp)) * C_ + g * CPG + c] = v;
        }
        __syncthreads();
    }
}

// ---------------------------------------------------------------- LayerNorm
__global__ __launch_bounds__(256) void layernorm_kernel(
    const float* __restrict__ in, const float* __restrict__ g,
    const float* __restrict__ b, float* __restrict__ out)
{
    const int row  = blockIdx.x * 8 + (threadIdx.x >> 5);
    const int lane = threadIdx.x & 31;
    const float4* ip = (const float4*)(in + (size_t)row * D_);
    float4 v[4];
    float s = 0.f, ss = 0.f;
#pragma unroll
    for (int i = 0; i < 4; i++) {
        v[i] = ip[lane + 32 * i];
        s  += v[i].x + v[i].y + v[i].z + v[i].w;
        ss += v[i].x*v[i].x + v[i].y*v[i].y + v[i].z*v[i].z + v[i].w*v[i].w;
    }
#pragma unroll
    for (int o = 16; o > 0; o >>= 1) {
        s  += __shfl_xor_sync(0xffffffffu, s, o);
        ss += __shfl_xor_sync(0xffffffffu, ss, o);
    }
    const float mu   = s * (1.f / D_);
    const float rstd = rsqrtf(ss * (1.f / D_) - mu * mu + 1e-5f);
    const float4* gp = (const float4*)g;
    const float4* bp = (const float4*)b;
    float4* op = (float4*)(out + (size_t)row * D_);
#pragma unroll
    for (int i = 0; i < 4; i++) {
        float4 gg = gp[lane + 32 * i], bb = bp[lane + 32 * i], o4;
        o4.x = (v[i].x - mu) * rstd * gg.x + bb.x;
        o4.y = (v[i].y - mu) * rstd * gg.y + bb.y;
        o4.z = (v[i].z - mu) * rstd * gg.z + bb.z;
        o4.w = (v[i].w - mu) * rstd * gg.w + bb.w;
        op[lane + 32 * i] = o4;
    }
}

// ================== Flash attention (tf32 mma.sync) =======================
// One CTA per (64-q tile, head, batch). 8 warps (4m x 2n).
// S = Q K^T via mma (m=q rows, n=keys);  O^T = V^T P^T via mma (m=d, n=q).
// Smem (floats): Qs[64][68] | Ks[2][64][68] | Vs[2][64][72] | Ps[64][68]
//                | mrow[64] lrow[64] arow[64]
#define AQS   0
#define AKS0  4352
#define AKS1  8704
#define AVS0  13056
#define AVS1  17664
#define APS   22272
#define AMR   26624
#define ALR   26688
#define AAR   26752
#define ATTN_SMEM_BYTES (26816 * 4)

__global__ __launch_bounds__(256, 2) void attn_kernel(
    const float* __restrict__ Q, const float* __restrict__ K,
    const float* __restrict__ V, float* __restrict__ O, int Lkv)
{
    extern __shared__ float sm[];
    const uint32_t sb = smem_u32(sm);
    const int tid = threadIdx.x;
    const int wid = tid >> 5, lane = tid & 31;
    const int lq = lane >> 2, lr = lane & 3;
    const int wm = wid >> 1, wn = wid & 1;
    const int r16 = tid >> 4, c16 = tid & 15;
    const int q0 = blockIdx.x * 64;
    const int h = blockIdx.y, b = blockIdx.z;
    const int nt = (Lkv + 63) >> 6;

    float* const Ps   = sm + APS;
    float* const mrow = sm + AMR;
    float* const lrow = sm + ALR;
    float* const arow = sm + AAR;

    // Q tile (never overwritten)
#pragma unroll
    for (int i = 0; i < 4; i++) {
        const int row = r16 + 16 * i;
        cp_async16(sb + (AQS + row * 68 + c16 * 4) * 4,
                   Q + ((size_t)(b * HW_ + q0 + row) * D_ + h * HD_ + c16 * 4),
                   16);
    }
    auto ISSUE_KV = [&](int t, int buf) {
        const int j0 = t << 6;
        const uint32_t kofs = buf ? AKS1 : AKS0;
        const uint32_t vofs = buf ? AVS1 : AVS0;
#pragma unroll
        for (int i = 0; i < 4; i++) {
            const int row = r16 + 16 * i;
            const int j = j0 + row;
            const int jc = (j < Lkv) ? j : (Lkv - 1);
            const int sz = (j < Lkv) ? 16 : 0;
            const size_t base = (size_t)(b * Lkv + jc) * D_ + h * HD_ + c16 * 4;
            cp_async16(sb + (kofs + row * 68 + c16 * 4) * 4, K + base, sz);
            cp_async16(sb + (vofs + row * 72 + c16 * 4) * 4, V + base, sz);
        }
    };
    ISSUE_KV(0, 0); CP_COMMIT();
    if (nt > 1) { ISSUE_KV(1, 1); CP_COMMIT(); }

    if (tid < 64) { mrow[tid] = -1e30f; lrow[tid] = 0.f; }

    float oacc[4][4];
#pragma unroll
    for (int in = 0; in < 4; in++)
#pragma unroll
        for (int r = 0; r < 4; r++) oacc[in][r] = 0.f;

    const int mr = wm * 16 + lq;   // q-row for S;  d-row for O^T

    for (int t = 0; t < nt; t++) {
        if (t + 1 < nt) CP_WAIT1(); else CP_WAIT0();
        __syncthreads();
        const float* const Ks = sm + ((t & 1) ? AKS1 : AKS0);
        const float* const Vs = sm + ((t & 1) ? AVS1 : AVS0);

        // ---- S = Q K^T ----
        float sacc[4][4];
#pragma unroll
        for (int in = 0; in < 4; in++)
#pragma unroll
            for (int r = 0; r < 4; r++) sacc[in][r] = 0.f;
#pragma unroll
        for (int ka = 0; ka < 8; ka++) {
            uint32_t af[4];
            af[0] = __float_as_uint(sm[AQS + mr * 68 + 8 * ka + lr]);
            af[1] = __float_as_uint(sm[AQS + (mr + 8) * 68 + 8 * ka + lr]);
            af[2] = __float_as_uint(sm[AQS + mr * 68 + 8 * ka + 4 + lr]);
            af[3] = __float_as_uint(sm[AQS + (mr + 8) * 68 + 8 * ka + 4 + lr]);
#pragma unroll
            for (int in = 0; in < 4; in++) {
                const int nr = wn * 32 + in * 8 + lq;
                uint32_t bf[2];
                bf[0] = __float_as_uint(Ks[nr * 68 + 8 * ka + lr]);
                bf[1] = __float_as_uint(Ks[nr * 68 + 8 * ka + 4 + lr]);
                mma_tf32(sacc[in], af, bf);
            }
        }
#pragma unroll
        for (int in = 0; in < 4; in++) {
            const int col = wn * 32 + in * 8 + 2 * lr;
            Ps[mr * 68 + col]           = sacc[in][0];
            Ps[mr * 68 + col + 1]       = sacc[in][1];
            Ps[(mr + 8) * 68 + col]     = sacc[in][2];
            Ps[(mr + 8) * 68 + col + 1] = sacc[in][3];
        }
        __syncthreads();

        // ---- online softmax (scale 0.125, mask, round P to tf32-RNA) ----
        {
            const int r = tid >> 2, p = tid & 3;
            const int j0 = t << 6;
            float cmax = -1e30f;
            for (int jj = p; jj < 64; jj += 4)
                if (j0 + jj < Lkv)
                    cmax = fmaxf(cmax, Ps[r * 68 + jj] * 0.125f);
            cmax = fmaxf(cmax, __shfl_xor_sync(0xffffffffu, cmax, 1));
            cmax = fmaxf(cmax, __shfl_xor_sync(0xffffffffu, cmax, 2));
            const float mold = mrow[r];
            const float mnew = fmaxf(mold, cmax);
            float csum = 0.f;
            for (int jj = p; jj < 64; jj += 4) {
                float e = (j0 + jj < Lkv)
                          ? __expf(Ps[r * 68 + jj] * 0.125f - mnew) : 0.f;
                e = __uint_as_float(f2tf32(e));   // consistent with mma
                Ps[r * 68 + jj] = e;
                csum += e;
            }
            csum += __shfl_xor_sync(0xffffffffu, csum, 1);
            csum += __shfl_xor_sync(0xffffffffu, csum, 2);
            if (p == 0) {
                const float al = __expf(mold - mnew);
                arow[r] = al;
                lrow[r] = lrow[r] * al + csum;
                mrow[r] = mnew;
            }
        }
        __syncthreads();

        // ---- rescale O acc (cols = q) ----
#pragma unroll
        for (int in = 0; in < 4; in++) {
            const int qc = wn * 32 + in * 8 + 2 * lr;
            const float a0 = arow[qc], a1 = arow[qc + 1];
            oacc[in][0] *= a0; oacc[in][1] *= a1;
            oacc[in][2] *= a0; oacc[in][3] *= a1;
        }
        // ---- O^T += V^T P^T ----
#pragma unroll
        for (int ka = 0; ka < 8; ka++) {
            uint32_t af[4];
            af[0] = __float_as_uint(Vs[(8 * ka + lr) * 72 + mr]);
            af[1] = __float_as_uint(Vs[(8 * ka + lr) * 72 + mr + 8]);
            af[2] = __float_as_uint(Vs[(8 * ka + 4 + lr) * 72 + mr]);
            af[3] = __float_as_uint(Vs[(8 * ka + 4 + lr) * 72 + mr + 8]);
#pragma unroll
            for (int in = 0; in < 4; in++) {
                const int qr = wn * 32 + in * 8 + lq;
                uint32_t bf[2];
                bf[0] = __float_as_uint(Ps[qr * 68 + 8 * ka + lr]);
                bf[1] = __float_as_uint(Ps[qr * 68 + 8 * ka + 4 + lr]);
                mma_tf32(oacc[in], af, bf);
            }
        }
        __syncthreads();
        if (t + 2 < nt) { ISSUE_KV(t + 2, t & 1); CP_COMMIT(); }
    }

    // ---- normalize by l, stage O^T, write coalesced ----
#pragma unroll
    for (int in = 0; in < 4; in++) {
        const int qc = wn * 32 + in * 8 + 2 * lr;
        const float i0 = 1.f / lrow[qc], i1 = 1.f / lrow[qc + 1];
        Ps[mr * 68 + qc]           = oacc[in][0] * i0;
        Ps[mr * 68 + qc + 1]       = oacc[in][1] * i1;
        Ps[(mr + 8) * 68 + qc]     = oacc[in][2] * i0;
        Ps[(mr + 8) * 68 + qc + 1] = oacc[in][3] * i1;
    }
    __syncthreads();
    const int qq = tid >> 2, dg = tid & 3;
#pragma unroll
    for (int g = 0; g < 4; g++) {
        const int d0 = g * 16 + dg * 4;
        float4 v;
        v.x = Ps[(d0 + 0) * 68 + qq];
        v.y = Ps[(d0 + 1) * 68 + qq];
        v.z = Ps[(d0 + 2) * 68 + qq];
        v.w = Ps[(d0 + 3) * 68 + qq];
        *(float4*)(O + (size_t)(b * HW_ + q0 + qq) * D_ + h * HD_ + d0) = v;
    }
}

// ------------------------------------------------------------------ driver
extern "C" void kernel_launch(void* const* d_in, const int* in_sizes, int n_in,
                              void* d_out, int out_size)
{
    const float* x         = (const float*)d_in[0];
    const float* ctx       = (const float*)d_in[1];
    const float* gn_g      = (const float*)d_in[2];
    const float* gn_b      = (const float*)d_in[3];
    const float* proj_in_w = (const float*)d_in[4];
    const float* proj_in_b = (const float*)d_in[5];
    const float* ln1_g = (const float*)d_in[6];
    const float* ln1_b = (const float*)d_in[7];
    const float* q1_w  = (const float*)d_in[8];
    const float* k1_w  = (const float*)d_in[9];
    const float* v1_w  = (const float*)d_in[10];
    const float* o1_w  = (const float*)d_in[11];
    const float* o1_b  = (const float*)d_in[12];
    const float* ln2_g = (const float*)d_in[13];
    const float* ln2_b = (const float*)d_in[14];
    const float* q2_w  = (const float*)d_in[15];
    const float* k2_w  = (const float*)d_in[16];
    const float* v2_w  = (const float*)d_in[17];
    const float* o2_w  = (const float*)d_in[18];
    const float* o2_b  = (const float*)d_in[19];
    const float* ln3_g = (const float*)d_in[20];
    const float* ln3_b = (const float*)d_in[21];
    const float* ff1_w = (const float*)d_in[22];
    const float* ff1_b = (const float*)d_in[23];
    const float* ff2_w = (const float*)d_in[24];
    const float* ff2_b = (const float*)d_in[25];
    const float* po_w  = (const float*)d_in[26];
    const float* po_b  = (const float*)d_in[27];
    float* out = (float*)d_out;

    float *pH, *pX, *pQ, *pK, *pV, *pA, *pF, *pWT;
    cudaGetSymbolAddress((void**)&pH, g_H);
    cudaGetSymbolAddress((void**)&pX, g_X);
    cudaGetSymbolAddress((void**)&pQ, g_Q);
    cudaGetSymbolAddress((void**)&pK, g_K);
    cudaGetSymbolAddress((void**)&pV, g_V);
    cudaGetSymbolAddress((void**)&pA, g_A);
    cudaGetSymbolAddress((void**)&pF, g_F);
    cudaGetSymbolAddress((void**)&pWT, g_WT);

    cudaFuncSetAttribute(attn_kernel,
                         cudaFuncAttributeMaxDynamicSharedMemorySize,
                         ATTN_SMEM_BYTES);
    cudaFuncSetAttribute(tc_gemm_kernel,
                         cudaFuncAttributeMaxDynamicSharedMemorySize,
                         GEMM_SMEM_BYTES);

    const dim3 tb(32, 8);
    const dim3 g512(D_ / 128, M_ / 128);              // 4 x 64
    const dim3 gctx(D_ / 128, (B_ * L_ + 127) / 128); // 4 x 5
    const dim3 gff(FF_ / 128, M_ / 128);              // 16 x 64
    const dim3 gattn(HW_ / 64, NH_, B_);
    const int SB = GEMM_SMEM_BYTES;

    // Launch order keeps the proj_in GEMM as launch #6 for ncu (-s 5 -c 1).
    groupnorm_kernel<<<B_ * 32, 256>>>(x, gn_g, gn_b, pX);                      // 1
    transpose_kernel<<<dim3(D_/32, C_/32),  tb>>>(proj_in_w, pWT + OF_PIN, C_, D_); // 2
    transpose_kernel<<<dim3(D_/32, D_/32),  tb>>>(q1_w,  pWT + OF_Q1,  D_,  D_);    // 3
    transpose_kernel<<<dim3(D_/32, D_/32),  tb>>>(k1_w,  pWT + OF_K1,  D_,  D_);    // 4
    transpose_kernel<<<dim3(D_/32, D_/32),  tb>>>(v1_w,  pWT + OF_V1,  D_,  D_);    // 5
    tc_gemm_kernel<<<g512, 256, SB>>>(pX, pWT + OF_PIN, proj_in_b, nullptr,
                                      pH, M_, D_, C_, 0);                       // 6 (profiled)
    transpose_kernel<<<dim3(D_/32, D_/32),  tb>>>(o1_w,  pWT + OF_O1,  D_,  D_);
    transpose_kernel<<<dim3(D_/32, D_/32),  tb>>>(q2_w,  pWT + OF_Q2,  D_,  D_);
    transpose_kernel<<<dim3(D_/32, DC_/32), tb>>>(k2_w,  pWT + OF_K2,  DC_, D_);
    transpose_kernel<<<dim3(D_/32, DC_/32), tb>>>(v2_w,  pWT + OF_V2,  DC_, D_);
    transpose_kernel<<<dim3(D_/32, D_/32),  tb>>>(o2_w,  pWT + OF_O2,  D_,  D_);
    transpose_kernel<<<dim3(FF_/32, D_/32), tb>>>(ff1_w, pWT + OF_FF1, D_,  FF_);
    transpose_kernel<<<dim3(D_/32, FF_/32), tb>>>(ff2_w, pWT + OF_FF2, FF_, D_);
    transpose_kernel<<<dim3(C_/32, D_/32),  tb>>>(po_w,  pWT + OF_PO,  D_,  C_);

    // --- self attention ---
    layernorm_kernel<<<M_ / 8, 256>>>(pH, ln1_g, ln1_b, pX);
    tc_gemm_kernel<<<g512, 256, SB>>>(pX, pWT + OF_Q1, nullptr, nullptr, pQ, M_, D_, D_, 0);
    tc_gemm_kernel<<<g512, 256, SB>>>(pX, pWT + OF_K1, nullptr, nullptr, pK, M_, D_, D_, 0);
    tc_gemm_kernel<<<g512, 256, SB>>>(pX, pWT + OF_V1, nullptr, nullptr, pV, M_, D_, D_, 0);
    attn_kernel<<<gattn, 256, ATTN_SMEM_BYTES>>>(pQ, pK, pV, pA, HW_);
    tc_gemm_kernel<<<g512, 256, SB>>>(pA, pWT + OF_O1, o1_b, pH, pH, M_, D_, D_, 2);

    // --- cross attention ---
    layernorm_kernel<<<M_ / 8, 256>>>(pH, ln2_g, ln2_b, pX);
    tc_gemm_kernel<<<g512, 256, SB>>>(pX, pWT + OF_Q2, nullptr, nullptr, pQ, M_, D_, D_, 0);
    tc_gemm_kernel<<<gctx, 256, SB>>>(ctx, pWT + OF_K2, nullptr, nullptr, pK, B_ * L_, D_, DC_, 0);
    tc_gemm_kernel<<<gctx, 256, SB>>>(ctx, pWT + OF_V2, nullptr, nullptr, pV, B_ * L_, D_, DC_, 0);
    attn_kernel<<<gattn, 256, ATTN_SMEM_BYTES>>>(pQ, pK, pV, pA, L_);
    tc_gemm_kernel<<<g512, 256, SB>>>(pA, pWT + OF_O2, o2_b, pH, pH, M_, D_, D_, 2);

    // --- feed forward ---
    layernorm_kernel<<<M_ / 8, 256>>>(pH, ln3_g, ln3_b, pX);
    tc_gemm_kernel<<<gff, 256, SB>>>(pX, pWT + OF_FF1, ff1_b, nullptr, pF, M_, FF_, D_, 1);
    tc_gemm_kernel<<<g512, 256, SB>>>(pF, pWT + OF_FF2, ff2_b, pH, pH, M_, D_, FF_, 2);

    // --- proj_out + input residual, write BCHW ---
    tc_gemm_kernel<<<g512, 256, SB>>>(pH, pWT + OF_PO, po_b, x, out, M_, D_, D_, 3);
}

// round 13
// speedup vs baseline: 3.5364x; 1.4917x over previous
#include <cuda_runtime.h>
#include <math.h>
#include <stdint.h>

// Problem constants
#define B_   8
#define C_   512
#define HW_  1024
#define D_   512
#define NH_  8
#define HD_  64
#define L_   77
#define DC_  768
#define FF_  2048
#define M_   (B_ * HW_)   // 8192 tokens

// ---------------- scratch (no allocation allowed -> __device__ globals) ----
__device__ float g_H[(size_t)M_ * D_];   // running hidden state
__device__ float g_X[(size_t)M_ * D_];   // GN / LN outputs
__device__ float g_Q[(size_t)M_ * D_];
__device__ float g_K[(size_t)M_ * D_];
__device__ float g_V[(size_t)M_ * D_];
__device__ float g_A[(size_t)M_ * D_];   // attention output
__device__ float g_F[(size_t)M_ * FF_];  // FF hidden

// ======================= PTX helpers =====================================
__device__ __forceinline__ uint32_t smem_u32(const void* p) {
    uint32_t a;
    asm("{ .reg .u64 t; cvta.to.shared.u64 t, %1; cvt.u32.u64 %0, t; }"
        : "=r"(a) : "l"(p));
    return a;
}

__device__ __forceinline__ void cp_async16(uint32_t dst, const void* src,
                                           int src_sz) {
    asm volatile("cp.async.cg.shared.global [%0], [%1], 16, %2;\n"
                 :: "r"(dst), "l"(src), "r"(src_sz));
}
#define CP_COMMIT() asm volatile("cp.async.commit_group;\n" ::: "memory")
#define CP_WAIT1()  asm volatile("cp.async.wait_group 1;\n" ::: "memory")
#define CP_WAIT0()  asm volatile("cp.async.wait_group 0;\n" ::: "memory")

__device__ __forceinline__ uint32_t f2tf32(float f) {
    uint32_t o;
    asm("cvt.rna.tf32.f32 %0, %1;" : "=r"(o) : "f"(f));
    return o;
}

__device__ __forceinline__ void mma_tf32(float* d, const uint32_t* a,
                                         const uint32_t* b) {
    asm volatile(
        "mma.sync.aligned.m16n8k8.row.col.f32.tf32.tf32.f32 "
        "{%0,%1,%2,%3}, {%4,%5,%6,%7}, {%8,%9}, {%0,%1,%2,%3};\n"
        : "+f"(d[0]), "+f"(d[1]), "+f"(d[2]), "+f"(d[3])
        : "r"(a[0]), "r"(a[1]), "r"(a[2]), "r"(a[3]),
          "r"(b[0]), "r"(b[1]));
}

// ======================= tensor-core tf32 GEMM ============================
// out[M,N] = A[M,K] @ W[K,N] (+bias), W read DIRECTLY in [K,N] layout.
// Modes: 0 bias; 1 bias+GELU; 2 bias+resid[M,N]; 3 BCHW out + bias + resid.
// CTA 128x128, 8 warps (4m x 2n), warp tile 32x64, K chunk 32.
// 3-stage cp.async pipeline, ONE barrier per chunk.
// Smem per stage: A [128 m][36] (bank 4*lq+lr, conflict-free)
//                 B [32 k][136] (bank 8*lr+lq, conflict-free)
#define A_WORDS 4608            // 128*36
#define B_WORDS 4352            // 32*136
#define STAGE_WORDS 8960
#define GEMM_SMEM_BYTES (3 * STAGE_WORDS * 4)   // 107520

__global__ __launch_bounds__(256, 2) void tc_gemm_kernel(
    const float* __restrict__ A, const float* __restrict__ W,
    const float* __restrict__ bias, const float* __restrict__ resid,
    float* __restrict__ out, int M, int N, int K, int mode)
{
    extern __shared__ char smem[];
    float* const smemf = (float*)smem;
    const uint32_t sb = smem_u32(smem);

    const int tid  = threadIdx.x;
    const int wid  = tid >> 5, lane = tid & 31;
    const int m0   = blockIdx.y * 128;
    const int n0   = blockIdx.x * 128;
    const int wm   = wid >> 1, wn = wid & 1;
    const int lq   = lane >> 2, lr = lane & 3;
    const int nchunk = K >> 5;

    float acc[2][8][4];
#pragma unroll
    for (int i = 0; i < 2; i++)
#pragma unroll
        for (int j = 0; j < 8; j++)
#pragma unroll
            for (int r = 0; r < 4; r++) acc[i][j][r] = 0.f;

    auto ISSUE = [&](int ck, int s) {
        const int k0 = ck << 5;
        const uint32_t ab = (uint32_t)(s * STAGE_WORDS);
        const uint32_t bb = ab + A_WORDS;
#pragma unroll
        for (int i = 0; i < 4; i++) {
            const int c = tid + 256 * i;
            const int m = c >> 3, kq = c & 7;
            cp_async16(sb + (ab + m * 36 + kq * 4) * 4,
                       A + (size_t)(m0 + m) * K + k0 + kq * 4,
                       (m0 + m < M) ? 16 : 0);
        }
#pragma unroll
        for (int i = 0; i < 4; i++) {
            const int c = tid + 256 * i;
            const int kk = c >> 5, nq = c & 31;
            cp_async16(sb + (bb + kk * 136 + nq * 4) * 4,
                       W + (size_t)(k0 + kk) * N + n0 + nq * 4, 16);
        }
    };
    auto COMPUTE = [&](int s) {
        const float* const sa  = smemf + s * STAGE_WORDS;
        const float* const sbp = sa + A_WORDS;
#pragma unroll
        for (int ka = 0; ka < 4; ka++) {
            uint32_t af[2][4], bf[8][2];
#pragma unroll
            for (int im = 0; im < 2; im++) {
                const int mrow = wm * 32 + im * 16 + lq;
                af[im][0] = __float_as_uint(sa[mrow * 36 + 8 * ka + lr]);
                af[im][1] = __float_as_uint(sa[(mrow + 8) * 36 + 8 * ka + lr]);
                af[im][2] = __float_as_uint(sa[mrow * 36 + 8 * ka + 4 + lr]);
                af[im][3] = __float_as_uint(sa[(mrow + 8) * 36 + 8 * ka + 4 + lr]);
            }
#pragma unroll
            for (int in = 0; in < 8; in++) {
                const int nn = wn * 64 + in * 8 + lq;
                bf[in][0] = __float_as_uint(sbp[(8 * ka + lr) * 136 + nn]);
                bf[in][1] = __float_as_uint(sbp[(8 * ka + 4 + lr) * 136 + nn]);
            }
#pragma unroll
            for (int im = 0; im < 2; im++)
#pragma unroll
                for (int in = 0; in < 8; in++)
                    mma_tf32(acc[im][in], af[im], bf[in]);
        }
    };

    ISSUE(0, 0); CP_COMMIT();
    if (nchunk > 1) { ISSUE(1, 1); CP_COMMIT(); }
    int st3 = 2;                       // stage for next issue
    for (int ck = 0; ck < nchunk; ck++) {
        if (ck + 1 < nchunk) CP_WAIT1(); else CP_WAIT0();
        __syncthreads();
        if (ck + 2 < nchunk) {
            ISSUE(ck + 2, st3); CP_COMMIT();
            st3 = (st3 == 2) ? 0 : st3 + 1;
        }
        COMPUTE(ck - 3 * ((ck * 0x5556) >> 16));   // ck % 3 (ck < 21845)
    }
    __syncthreads();

    // ---- stage accumulators to smem [128][132] ----
    float* const stg = smemf;
    const int tq = lane & 3;
#pragma unroll
    for (int im = 0; im < 2; im++)
#pragma unroll
        for (int in = 0; in < 8; in++) {
            const int row = wm * 32 + im * 16 + lq;
            const int col = wn * 64 + in * 8 + tq * 2;
            *(float2*)&stg[row * 132 + col] =
                make_float2(acc[im][in][0], acc[im][in][1]);
            *(float2*)&stg[(row + 8) * 132 + col] =
                make_float2(acc[im][in][2], acc[im][in][3]);
        }
    __syncthreads();

    if (mode == 3) {
        const int bimg = m0 >> 10, hw0 = m0 & 1023;
        const int hw4 = lane * 4;
#pragma unroll
        for (int j = 0; j < 16; j++) {
            const int nc = wid + 8 * j;
            const int n = n0 + nc;
            const float bj = bias[n];
            const size_t base = ((size_t)(bimg * C_ + n)) * HW_ + hw0 + hw4;
            float4 rv = *(const float4*)(resid + base);
            float4 o;
            o.x = stg[(hw4 + 0) * 132 + nc] + bj + rv.x;
            o.y = stg[(hw4 + 1) * 132 + nc] + bj + rv.y;
            o.z = stg[(hw4 + 2) * 132 + nc] + bj + rv.z;
            o.w = stg[(hw4 + 3) * 132 + nc] + bj + rv.w;
            *(float4*)(out + base) = o;
        }
    } else {
        float4 bv = make_float4(0.f, 0.f, 0.f, 0.f);
        if (bias) bv = *(const float4*)(bias + n0 + lane * 4);
#pragma unroll 1
        for (int stp = 0; stp < 16; stp++) {
            const int rr = wid + 8 * stp;
            const int m = m0 + rr;
            if (m >= M) continue;
            float4 v = *(float4*)&stg[rr * 132 + lane * 4];
            v.x += bv.x; v.y += bv.y; v.z += bv.z; v.w += bv.w;
            if (mode == 1) {
                v.x = 0.5f * v.x * (1.f + erff(v.x * 0.70710678118654752f));
                v.y = 0.5f * v.y * (1.f + erff(v.y * 0.70710678118654752f));
                v.z = 0.5f * v.z * (1.f + erff(v.z * 0.70710678118654752f));
                v.w = 0.5f * v.w * (1.f + erff(v.w * 0.70710678118654752f));
            } else if (mode == 2) {
                float4 rv = *(const float4*)(resid + (size_t)m * N + n0 + lane * 4);
                v.x += rv.x; v.y += rv.y; v.z += rv.z; v.w += rv.w;
            }
            *(float4*)(out + (size_t)m * N + n0 + lane * 4) = v;
        }
    }
}

// ---------------------------------------------------------------- GroupNorm
__global__ __launch_bounds__(256) void groupnorm_kernel(
    const float* __restrict__ x, const float* __restrict__ gam,
    const float* __restrict__ bet, float* __restrict__ out)
{
    const int b = blockIdx.x >> 5;
    const int g = blockIdx.x & 31;
    const int CPG = 16;
    const float* base = x + ((size_t)(b * C_ + g * CPG)) * HW_;
    const int tid = threadIdx.x;

    float s = 0.f, ss = 0.f;
    for (int i = tid; i < CPG * HW_; i += 256) {
        float v = base[i];
        s += v; ss += v * v;
    }
    __shared__ float red[256], red2[256];
    red[tid] = s; red2[tid] = ss;
    __syncthreads();
    for (int st = 128; st > 0; st >>= 1) {
        if (tid < st) { red[tid] += red[tid + st]; red2[tid] += red2[tid + st]; }
        __syncthreads();
    }
    __shared__ float s_mu, s_rstd;
    if (tid == 0) {
        float mu  = red[0] / (CPG * HW_);
        float var = red2[0] / (CPG * HW_) - mu * mu;
        s_mu = mu;
        s_rstd = rsqrtf(var + 1e-5f);
    }
    __shared__ float gv[16], bv[16];
    if (tid < 16) { gv[tid] = gam[g * CPG + tid]; bv[tid] = bet[g * CPG + tid]; }
    __syncthreads();
    const float mu = s_mu, rstd = s_rstd;

    __shared__ float tile[16][65];
    for (int s0 = 0; s0 < HW_; s0 += 64) {
        for (int i = tid; i < 16 * 64; i += 256) {
            int c = i >> 6, sp = i & 63;
            tile[c][sp] = base[(size_t)c * HW_ + s0 + sp];
        }
        __syncthreads();
        for (int i = tid; i < 16 * 64; i += 256) {
            int c = i & 15, sp = i >> 4;
            float v = (tile[c][sp] - mu) * rstd * gv[c] + bv[c];
            out[((size_t)(b * HW_ + s0 + sp)) * C_ + g * CPG + c] = v;
        }
        __syncthreads();
    }
}

// ---------------------------------------------------------------- LayerNorm
__global__ __launch_bounds__(256) void layernorm_kernel(
    const float* __restrict__ in, const float* __restrict__ g,
    const float* __restrict__ b, float* __restrict__ out)
{
    const int row  = blockIdx.x * 8 + (threadIdx.x >> 5);
    const int lane = threadIdx.x & 31;
    const float4* ip = (const float4*)(in + (size_t)row * D_);
    float4 v[4];
    float s = 0.f, ss = 0.f;
#pragma unroll
    for (int i = 0; i < 4; i++) {
        v[i] = ip[lane + 32 * i];
        s  += v[i].x + v[i].y + v[i].z + v[i].w;
        ss += v[i].x*v[i].x + v[i].y*v[i].y + v[i].z*v[i].z + v[i].w*v[i].w;
    }
#pragma unroll
    for (int o = 16; o > 0; o >>= 1) {
        s  += __shfl_xor_sync(0xffffffffu, s, o);
        ss += __shfl_xor_sync(0xffffffffu, ss, o);
    }
    const float mu   = s * (1.f / D_);
    const float rstd = rsqrtf(ss * (1.f / D_) - mu * mu + 1e-5f);
    const float4* gp = (const float4*)g;
    const float4* bp = (const float4*)b;
    float4* op = (float4*)(out + (size_t)row * D_);
#pragma unroll
    for (int i = 0; i < 4; i++) {
        float4 gg = gp[lane + 32 * i], bb = bp[lane + 32 * i], o4;
        o4.x = (v[i].x - mu) * rstd * gg.x + bb.x;
        o4.y = (v[i].y - mu) * rstd * gg.y + bb.y;
        o4.z = (v[i].z - mu) * rstd * gg.z + bb.z;
        o4.w = (v[i].w - mu) * rstd * gg.w + bb.w;
        op[lane + 32 * i] = o4;
    }
}

// ================== Flash attention (tf32 mma.sync) =======================
#define AQS   0
#define AKS0  4352
#define AKS1  8704
#define AVS0  13056
#define AVS1  17664
#define APS   22272
#define AMR   26624
#define ALR   26688
#define AAR   26752
#define ATTN_SMEM_BYTES (26816 * 4)

__global__ __launch_bounds__(256, 2) void attn_kernel(
    const float* __restrict__ Q, const float* __restrict__ K,
    const float* __restrict__ V, float* __restrict__ O, int Lkv)
{
    extern __shared__ float sm[];
    const uint32_t sb = smem_u32(sm);
    const int tid = threadIdx.x;
    const int wid = tid >> 5, lane = tid & 31;
    const int lq = lane >> 2, lr = lane & 3;
    const int wm = wid >> 1, wn = wid & 1;
    const int r16 = tid >> 4, c16 = tid & 15;
    const int q0 = blockIdx.x * 64;
    const int h = blockIdx.y, b = blockIdx.z;
    const int nt = (Lkv + 63) >> 6;

    float* const Ps   = sm + APS;
    float* const mrow = sm + AMR;
    float* const lrow = sm + ALR;
    float* const arow = sm + AAR;

#pragma unroll
    for (int i = 0; i < 4; i++) {
        const int row = r16 + 16 * i;
        cp_async16(sb + (AQS + row * 68 + c16 * 4) * 4,
                   Q + ((size_t)(b * HW_ + q0 + row) * D_ + h * HD_ + c16 * 4),
                   16);
    }
    auto ISSUE_KV = [&](int t, int buf) {
        const int j0 = t << 6;
        const uint32_t kofs = buf ? AKS1 : AKS0;
        const uint32_t vofs = buf ? AVS1 : AVS0;
#pragma unroll
        for (int i = 0; i < 4; i++) {
            const int row = r16 + 16 * i;
            const int j = j0 + row;
            const int jc = (j < Lkv) ? j : (Lkv - 1);
            const int sz = (j < Lkv) ? 16 : 0;
            const size_t base = (size_t)(b * Lkv + jc) * D_ + h * HD_ + c16 * 4;
            cp_async16(sb + (kofs + row * 68 + c16 * 4) * 4, K + base, sz);
            cp_async16(sb + (vofs + row * 72 + c16 * 4) * 4, V + base, sz);
        }
    };
    ISSUE_KV(0, 0); CP_COMMIT();
    if (nt > 1) { ISSUE_KV(1, 1); CP_COMMIT(); }

    if (tid < 64) { mrow[tid] = -1e30f; lrow[tid] = 0.f; }

    float oacc[4][4];
#pragma unroll
    for (int in = 0; in < 4; in++)
#pragma unroll
        for (int r = 0; r < 4; r++) oacc[in][r] = 0.f;

    const int mr = wm * 16 + lq;

    for (int t = 0; t < nt; t++) {
        if (t + 1 < nt) CP_WAIT1(); else CP_WAIT0();
        __syncthreads();
        const float* const Ks = sm + ((t & 1) ? AKS1 : AKS0);
        const float* const Vs = sm + ((t & 1) ? AVS1 : AVS0);

        float sacc[4][4];
#pragma unroll
        for (int in = 0; in < 4; in++)
#pragma unroll
            for (int r = 0; r < 4; r++) sacc[in][r] = 0.f;
#pragma unroll
        for (int ka = 0; ka < 8; ka++) {
            uint32_t af[4];
            af[0] = __float_as_uint(sm[AQS + mr * 68 + 8 * ka + lr]);
            af[1] = __float_as_uint(sm[AQS + (mr + 8) * 68 + 8 * ka + lr]);
            af[2] = __float_as_uint(sm[AQS + mr * 68 + 8 * ka + 4 + lr]);
            af[3] = __float_as_uint(sm[AQS + (mr + 8) * 68 + 8 * ka + 4 + lr]);
#pragma unroll
            for (int in = 0; in < 4; in++) {
                const int nr = wn * 32 + in * 8 + lq;
                uint32_t bf[2];
                bf[0] = __float_as_uint(Ks[nr * 68 + 8 * ka + lr]);
                bf[1] = __float_as_uint(Ks[nr * 68 + 8 * ka + 4 + lr]);
                mma_tf32(sacc[in], af, bf);
            }
        }
#pragma unroll
        for (int in = 0; in < 4; in++) {
            const int col = wn * 32 + in * 8 + 2 * lr;
            Ps[mr * 68 + col]           = sacc[in][0];
            Ps[mr * 68 + col + 1]       = sacc[in][1];
            Ps[(mr + 8) * 68 + col]     = sacc[in][2];
            Ps[(mr + 8) * 68 + col + 1] = sacc[in][3];
        }
        __syncthreads();

        {
            const int r = tid >> 2, p = tid & 3;
            const int j0 = t << 6;
            float cmax = -1e30f;
            for (int jj = p; jj < 64; jj += 4)
                if (j0 + jj < Lkv)
                    cmax = fmaxf(cmax, Ps[r * 68 + jj] * 0.125f);
            cmax = fmaxf(cmax, __shfl_xor_sync(0xffffffffu, cmax, 1));
            cmax = fmaxf(cmax, __shfl_xor_sync(0xffffffffu, cmax, 2));
            const float mold = mrow[r];
            const float mnew = fmaxf(mold, cmax);
            float csum = 0.f;
            for (int jj = p; jj < 64; jj += 4) {
                float e = (j0 + jj < Lkv)
                          ? __expf(Ps[r * 68 + jj] * 0.125f - mnew) : 0.f;
                e = __uint_as_float(f2tf32(e));
                Ps[r * 68 + jj] = e;
                csum += e;
            }
            csum += __shfl_xor_sync(0xffffffffu, csum, 1);
            csum += __shfl_xor_sync(0xffffffffu, csum, 2);
            if (p == 0) {
                const float al = __expf(mold - mnew);
                arow[r] = al;
                lrow[r] = lrow[r] * al + csum;
                mrow[r] = mnew;
            }
        }
        __syncthreads();

#pragma unroll
        for (int in = 0; in < 4; in++) {
            const int qc = wn * 32 + in * 8 + 2 * lr;
            const float a0 = arow[qc], a1 = arow[qc + 1];
            oacc[in][0] *= a0; oacc[in][1] *= a1;
            oacc[in][2] *= a0; oacc[in][3] *= a1;
        }
#pragma unroll
        for (int ka = 0; ka < 8; ka++) {
            uint32_t af[4];
            af[0] = __float_as_uint(Vs[(8 * ka + lr) * 72 + mr]);
            af[1] = __float_as_uint(Vs[(8 * ka + lr) * 72 + mr + 8]);
            af[2] = __float_as_uint(Vs[(8 * ka + 4 + lr) * 72 + mr]);
            af[3] = __float_as_uint(Vs[(8 * ka + 4 + lr) * 72 + mr + 8]);
#pragma unroll
            for (int in = 0; in < 4; in++) {
                const int qr = wn * 32 + in * 8 + lq;
                uint32_t bf[2];
                bf[0] = __float_as_uint(Ps[qr * 68 + 8 * ka + lr]);
                bf[1] = __float_as_uint(Ps[qr * 68 + 8 * ka + 4 + lr]);
                mma_tf32(oacc[in], af, bf);
            }
        }
        __syncthreads();
        if (t + 2 < nt) { ISSUE_KV(t + 2, t & 1); CP_COMMIT(); }
    }

#pragma unroll
    for (int in = 0; in < 4; in++) {
        const int qc = wn * 32 + in * 8 + 2 * lr;
        const float i0 = 1.f / lrow[qc], i1 = 1.f / lrow[qc + 1];
        Ps[mr * 68 + qc]           = oacc[in][0] * i0;
        Ps[mr * 68 + qc + 1]       = oacc[in][1] * i1;
        Ps[(mr + 8) * 68 + qc]     = oacc[in][2] * i0;
        Ps[(mr + 8) * 68 + qc + 1] = oacc[in][3] * i1;
    }
    __syncthreads();
    const int qq = tid >> 2, dg = tid & 3;
#pragma unroll
    for (int g = 0; g < 4; g++) {
        const int d0 = g * 16 + dg * 4;
        float4 v;
        v.x = Ps[(d0 + 0) * 68 + qq];
        v.y = Ps[(d0 + 1) * 68 + qq];
        v.z = Ps[(d0 + 2) * 68 + qq];
        v.w = Ps[(d0 + 3) * 68 + qq];
        *(float4*)(O + (size_t)(b * HW_ + q0 + qq) * D_ + h * HD_ + d0) = v;
    }
}

// ------------------------------------------------------------------ driver
extern "C" void kernel_launch(void* const* d_in, const int* in_sizes, int n_in,
                              void* d_out, int out_size)
{
    const float* x         = (const float*)d_in[0];
    const float* ctx       = (const float*)d_in[1];
    const float* gn_g      = (const float*)d_in[2];
    const float* gn_b      = (const float*)d_in[3];
    const float* proj_in_w = (const float*)d_in[4];
    const float* proj_in_b = (const float*)d_in[5];
    const float* ln1_g = (const float*)d_in[6];
    const float* ln1_b = (const float*)d_in[7];
    const float* q1_w  = (const float*)d_in[8];
    const float* k1_w  = (const float*)d_in[9];
    const float* v1_w  = (const float*)d_in[10];
    const float* o1_w  = (const float*)d_in[11];
    const float* o1_b  = (const float*)d_in[12];
    const float* ln2_g = (const float*)d_in[13];
    const float* ln2_b = (const float*)d_in[14];
    const float* q2_w  = (const float*)d_in[15];
    const float* k2_w  = (const float*)d_in[16];
    const float* v2_w  = (const float*)d_in[17];
    const float* o2_w  = (const float*)d_in[18];
    const float* o2_b  = (const float*)d_in[19];
    const float* ln3_g = (const float*)d_in[20];
    const float* ln3_b = (const float*)d_in[21];
    const float* ff1_w = (const float*)d_in[22];
    const float* ff1_b = (const float*)d_in[23];
    const float* ff2_w = (const float*)d_in[24];
    const float* ff2_b = (const float*)d_in[25];
    const float* po_w  = (const float*)d_in[26];
    const float* po_b  = (const float*)d_in[27];
    float* out = (float*)d_out;

    float *pH, *pX, *pQ, *pK, *pV, *pA, *pF;
    cudaGetSymbolAddress((void**)&pH, g_H);
    cudaGetSymbolAddress((void**)&pX, g_X);
    cudaGetSymbolAddress((void**)&pQ, g_Q);
    cudaGetSymbolAddress((void**)&pK, g_K);
    cudaGetSymbolAddress((void**)&pV, g_V);
    cudaGetSymbolAddress((void**)&pA, g_A);
    cudaGetSymbolAddress((void**)&pF, g_F);

    cudaFuncSetAttribute(attn_kernel,
                         cudaFuncAttributeMaxDynamicSharedMemorySize,
                         ATTN_SMEM_BYTES);
    cudaFuncSetAttribute(tc_gemm_kernel,
                         cudaFuncAttributeMaxDynamicSharedMemorySize,
                         GEMM_SMEM_BYTES);

    const dim3 g512(D_ / 128, M_ / 128);              // 4 x 64
    const dim3 gctx(D_ / 128, (B_ * L_ + 127) / 128); // 4 x 5
    const dim3 gff(FF_ / 128, M_ / 128);              // 16 x 64
    const dim3 gattn(HW_ / 64, NH_, B_);
    const int SB = GEMM_SMEM_BYTES;

    // Launch order: the 5th launch (k1 GEMM) is what ncu (-s/-c) captures.
    groupnorm_kernel<<<B_ * 32, 256>>>(x, gn_g, gn_b, pX);                        // 1
    tc_gemm_kernel<<<g512, 256, SB>>>(pX, proj_in_w, proj_in_b, nullptr,
                                      pH, M_, D_, C_, 0);                         // 2
    layernorm_kernel<<<M_ / 8, 256>>>(pH, ln1_g, ln1_b, pX);                      // 3
    tc_gemm_kernel<<<g512, 256, SB>>>(pX, q1_w, nullptr, nullptr, pQ, M_, D_, D_, 0); // 4
    tc_gemm_kernel<<<g512, 256, SB>>>(pX, k1_w, nullptr, nullptr, pK, M_, D_, D_, 0); // 5 (profiled)
    tc_gemm_kernel<<<g512, 256, SB>>>(pX, v1_w, nullptr, nullptr, pV, M_, D_, D_, 0); // 6
    attn_kernel<<<gattn, 256, ATTN_SMEM_BYTES>>>(pQ, pK, pV, pA, HW_);
    tc_gemm_kernel<<<g512, 256, SB>>>(pA, o1_w, o1_b, pH, pH, M_, D_, D_, 2);

    // --- cross attention ---
    layernorm_kernel<<<M_ / 8, 256>>>(pH, ln2_g, ln2_b, pX);
    tc_gemm_kernel<<<g512, 256, SB>>>(pX, q2_w, nullptr, nullptr, pQ, M_, D_, D_, 0);
    tc_gemm_kernel<<<gctx, 256, SB>>>(ctx, k2_w, nullptr, nullptr, pK, B_ * L_, D_, DC_, 0);
    tc_gemm_kernel<<<gctx, 256, SB>>>(ctx, v2_w, nullptr, nullptr, pV, B_ * L_, D_, DC_, 0);
    attn_kernel<<<gattn, 256, ATTN_SMEM_BYTES>>>(pQ, pK, pV, pA, L_);
    tc_gemm_kernel<<<g512, 256, SB>>>(pA, o2_w, o2_b, pH, pH, M_, D_, D_, 2);

    // --- feed forward ---
    layernorm_kernel<<<M_ / 8, 256>>>(pH, ln3_g, ln3_b, pX);
    tc_gemm_kernel<<<gff, 256, SB>>>(pX, ff1_w, ff1_b, nullptr, pF, M_, FF_, D_, 1);
    tc_gemm_kernel<<<g512, 256, SB>>>(pF, ff2_w, ff2_b, pH, pH, M_, D_, FF_, 2);

    // --- proj_out + input residual, write BCHW ---
    tc_gemm_kernel<<<g512, 256, SB>>>(pH, po_w, po_b, x, out, M_, D_, D_, 3);
}